// round 1
// baseline (speedup 1.0000x reference)
#include <cuda_runtime.h>
#include <math.h>

#define S_LEN  2048
#define BATCH  2
#define DMODEL 1024
#define NHEADS 16
#define HDIM   64
#define M_ROWS (S_LEN * BATCH)   // 4096

// Scratch (allocation-free): 4 x 16 MB
__device__ float g_q[BATCH * NHEADS * S_LEN * HDIM];
__device__ float g_k[BATCH * NHEADS * S_LEN * HDIM];
__device__ float g_v[BATCH * NHEADS * S_LEN * HDIM];
__device__ float g_att[S_LEN * BATCH * DMODEL];

// ---------------------------------------------------------------------------
// Tiled fp32 GEMM body: C[64x64] per block, 256 threads, 4x4 micro-tile.
// A is [M_ROWS, DMODEL] row-major, W is [DMODEL, DMODEL] row-major.
// HEAD_OUT: write into [B, H, S, HD] head layout; else row-major [r, c].
// ---------------------------------------------------------------------------
template <bool HEAD_OUT>
__device__ __forceinline__ void gemm_body(const float* __restrict__ A,
                                          const float* __restrict__ W,
                                          const float* __restrict__ bias,
                                          float* __restrict__ out)
{
    __shared__ float As[16][68];   // As[k][m] (transposed for broadcast-free reads)
    __shared__ float Bs[16][68];   // Bs[k][n]

    const int tid = threadIdx.x;
    const int tx = tid & 15;       // 0..15 -> 4 output cols each
    const int ty = tid >> 4;       // 0..15 -> 4 output rows each
    const int m0 = blockIdx.y * 64;
    const int n0 = blockIdx.x * 64;

    const int arow = tid >> 2;          // 0..63
    const int acol = (tid & 3) * 4;     // 0,4,8,12
    const int brow = tid >> 4;          // 0..15
    const int bcol = (tid & 15) * 4;    // 0..60

    float acc[4][4] = {};

    for (int k0 = 0; k0 < DMODEL; k0 += 16) {
        float4 a = *(const float4*)&A[(m0 + arow) * DMODEL + k0 + acol];
        As[acol + 0][arow] = a.x;
        As[acol + 1][arow] = a.y;
        As[acol + 2][arow] = a.z;
        As[acol + 3][arow] = a.w;
        *(float4*)&Bs[brow][bcol] =
            *(const float4*)&W[(k0 + brow) * DMODEL + n0 + bcol];
        __syncthreads();

#pragma unroll
        for (int kk = 0; kk < 16; kk++) {
            float4 av = *(const float4*)&As[kk][ty * 4];
            float4 bv = *(const float4*)&Bs[kk][tx * 4];
            float ar[4] = {av.x, av.y, av.z, av.w};
            float br[4] = {bv.x, bv.y, bv.z, bv.w};
#pragma unroll
            for (int i = 0; i < 4; i++)
#pragma unroll
                for (int j = 0; j < 4; j++)
                    acc[i][j] = fmaf(ar[i], br[j], acc[i][j]);
        }
        __syncthreads();
    }

#pragma unroll
    for (int i = 0; i < 4; i++) {
        const int r = m0 + ty * 4 + i;
#pragma unroll
        for (int j = 0; j < 4; j++) {
            const int c = n0 + tx * 4 + j;
            const float v = acc[i][j] + bias[c];
            if (HEAD_OUT) {
                // r = s*BATCH + b ; c = h*HDIM + d
                const int s = r >> 1, b = r & 1;
                const int h = c >> 6, d = c & 63;
                out[(((b * NHEADS + h) * S_LEN) + s) * HDIM + d] = v;
            } else {
                out[r * DMODEL + c] = v;
            }
        }
    }
}

__global__ __launch_bounds__(256)
void qkv_kernel(const float* __restrict__ src,
                const float* __restrict__ wq, const float* __restrict__ bq,
                const float* __restrict__ wk, const float* __restrict__ bk,
                const float* __restrict__ wv, const float* __restrict__ bv)
{
    const float* W;
    const float* bs;
    float* out;
    if (blockIdx.z == 0)      { W = wq; bs = bq; out = g_q; }
    else if (blockIdx.z == 1) { W = wk; bs = bk; out = g_k; }
    else                      { W = wv; bs = bv; out = g_v; }
    gemm_body<true>(src, W, bs, out);
}

__global__ __launch_bounds__(256)
void outproj_kernel(const float* __restrict__ wo, const float* __restrict__ bo,
                    float* __restrict__ out)
{
    gemm_body<false>(g_att, wo, bo, out);
}

// ---------------------------------------------------------------------------
// Flash attention with additive edge bias + sign gating.
//   logits = (q.k) * 0.125 + bias[s,t]
//   attn   = softmax(logits) * sign(bias)   (sign folded into numerator only)
// Per block: one (b,h) and one 64-row query tile; iterate 32 key tiles of 64.
// ---------------------------------------------------------------------------
#define ATTN_SMEM (4 * 64 * 68 * 4)

__global__ __launch_bounds__(256, 2)
void attn_kernel(const float* __restrict__ bias2d)
{
    extern __shared__ float sm[];
    float* Qs = sm;                 // Qs[d*68 + m]   (d-major)
    float* Ks = sm + 64 * 68;       // Ks[d*68 + n]   (d-major)
    float* Vs = sm + 2 * 64 * 68;   // Vs[kc*68 + hd] (row-major)
    float* Ps = sm + 3 * 64 * 68;   // Ps[m*68 + kc]

    const int bh = blockIdx.y;            // 0..31
    const int b = bh >> 4, h = bh & 15;
    const int q0 = blockIdx.x * 64;
    const int tid = threadIdx.x;
    const int tx = tid & 15, ty = tid >> 4;

    const float* qb = g_q + (size_t)(b * NHEADS + h) * S_LEN * HDIM;
    const float* kb = g_k + (size_t)(b * NHEADS + h) * S_LEN * HDIM;
    const float* vb = g_v + (size_t)(b * NHEADS + h) * S_LEN * HDIM;

    const int lr = tid >> 4;          // loader row base 0..15
    const int lc = (tid & 15) * 4;    // loader col 0..60

    // Load Q tile, transposed to d-major
#pragma unroll
    for (int p = 0; p < 4; p++) {
        const int r = lr + p * 16;
        float4 qv = *(const float4*)&qb[(q0 + r) * HDIM + lc];
        Qs[(lc + 0) * 68 + r] = qv.x;
        Qs[(lc + 1) * 68 + r] = qv.y;
        Qs[(lc + 2) * 68 + r] = qv.z;
        Qs[(lc + 3) * 68 + r] = qv.w;
    }

    float mI[4], lI[4], O[4][4];
#pragma unroll
    for (int i = 0; i < 4; i++) {
        mI[i] = -INFINITY;
        lI[i] = 0.f;
#pragma unroll
        for (int j = 0; j < 4; j++) O[i][j] = 0.f;
    }

    for (int k0 = 0; k0 < S_LEN; k0 += 64) {
        __syncthreads();   // protect Ks/Vs/Ps from previous iteration's readers
        // Load K (transposed) and V (row-major) tiles
#pragma unroll
        for (int p = 0; p < 4; p++) {
            const int r = lr + p * 16;
            float4 kv = *(const float4*)&kb[(k0 + r) * HDIM + lc];
            Ks[(lc + 0) * 68 + r] = kv.x;
            Ks[(lc + 1) * 68 + r] = kv.y;
            Ks[(lc + 2) * 68 + r] = kv.z;
            Ks[(lc + 3) * 68 + r] = kv.w;
            *(float4*)&Vs[r * 68 + lc] = *(const float4*)&vb[(k0 + r) * HDIM + lc];
        }
        __syncthreads();

        // S tile: sv[i][j] = q[m].k[n], m = ty*4+i, n = tx*4+j
        float sv[4][4] = {};
#pragma unroll
        for (int d = 0; d < 64; d++) {
            float4 qv = *(const float4*)&Qs[d * 68 + ty * 4];
            float4 kv = *(const float4*)&Ks[d * 68 + tx * 4];
            float qr[4] = {qv.x, qv.y, qv.z, qv.w};
            float kr[4] = {kv.x, kv.y, kv.z, kv.w};
#pragma unroll
            for (int i = 0; i < 4; i++)
#pragma unroll
                for (int j = 0; j < 4; j++)
                    sv[i][j] = fmaf(qr[i], kr[j], sv[i][j]);
        }

        // scale + bias, record sign bits, row max
        unsigned sgn = 0;
        float rmax[4];
#pragma unroll
        for (int i = 0; i < 4; i++) {
            float4 bb = *(const float4*)&bias2d[(size_t)(q0 + ty * 4 + i) * S_LEN + k0 + tx * 4];
            float bz[4] = {bb.x, bb.y, bb.z, bb.w};
            rmax[i] = -INFINITY;
#pragma unroll
            for (int j = 0; j < 4; j++) {
                float lg = fmaf(sv[i][j], 0.125f, bz[j]);
                sv[i][j] = lg;
                if (bz[j] < 0.f) sgn |= 1u << (i * 4 + j);
                rmax[i] = fmaxf(rmax[i], lg);
            }
        }

        // online softmax update; store signed exp into Ps
#pragma unroll
        for (int i = 0; i < 4; i++) {
#pragma unroll
            for (int msk = 8; msk >= 1; msk >>= 1)
                rmax[i] = fmaxf(rmax[i], __shfl_xor_sync(0xffffffffu, rmax[i], msk));
            const float mn = fmaxf(mI[i], rmax[i]);
            const float al = __expf(mI[i] - mn);
            mI[i] = mn;
            lI[i] *= al;
#pragma unroll
            for (int j = 0; j < 4; j++) O[i][j] *= al;
#pragma unroll
            for (int j = 0; j < 4; j++) {
                const float e = __expf(sv[i][j] - mn);
                lI[i] += e;
                sv[i][j] = ((sgn >> (i * 4 + j)) & 1u) ? -e : e;
            }
            *(float4*)&Ps[(ty * 4 + i) * 68 + tx * 4] =
                make_float4(sv[i][0], sv[i][1], sv[i][2], sv[i][3]);
        }
        __syncthreads();

        // O += P @ V  (Ps reads broadcast across tx; Vs float4)
#pragma unroll
        for (int kc = 0; kc < 64; kc++) {
            float pr[4];
#pragma unroll
            for (int i = 0; i < 4; i++) pr[i] = Ps[(ty * 4 + i) * 68 + kc];
            float4 vv = *(const float4*)&Vs[kc * 68 + tx * 4];
            float vr[4] = {vv.x, vv.y, vv.z, vv.w};
#pragma unroll
            for (int i = 0; i < 4; i++)
#pragma unroll
                for (int j = 0; j < 4; j++)
                    O[i][j] = fmaf(pr[i], vr[j], O[i][j]);
        }
    }

    // finalize: reduce denominator across tx, divide, write [S,B,D] layout
#pragma unroll
    for (int i = 0; i < 4; i++) {
#pragma unroll
        for (int msk = 8; msk >= 1; msk >>= 1)
            lI[i] += __shfl_xor_sync(0xffffffffu, lI[i], msk);
        const float inv = 1.f / lI[i];
        const int srow = q0 + ty * 4 + i;
        float4 o4 = make_float4(O[i][0] * inv, O[i][1] * inv,
                                O[i][2] * inv, O[i][3] * inv);
        *(float4*)&g_att[(size_t)(srow * BATCH + b) * DMODEL + h * HDIM + tx * 4] = o4;
    }
}

// ---------------------------------------------------------------------------
extern "C" void kernel_launch(void* const* d_in, const int* in_sizes, int n_in,
                              void* d_out, int out_size)
{
    const float* src    = (const float*)d_in[0];
    const float* bias2d = (const float*)d_in[1];
    const float* wq = (const float*)d_in[2];
    const float* bq = (const float*)d_in[3];
    const float* wk = (const float*)d_in[4];
    const float* bk = (const float*)d_in[5];
    const float* wv = (const float*)d_in[6];
    const float* bv = (const float*)d_in[7];
    const float* wo = (const float*)d_in[8];
    const float* bo = (const float*)d_in[9];
    float* out = (float*)d_out;

    cudaFuncSetAttribute(attn_kernel,
                         cudaFuncAttributeMaxDynamicSharedMemorySize, ATTN_SMEM);

    dim3 gproj(DMODEL / 64, M_ROWS / 64, 3);
    qkv_kernel<<<gproj, 256>>>(src, wq, bq, wk, bk, wv, bv);

    dim3 gattn(S_LEN / 64, BATCH * NHEADS);
    attn_kernel<<<gattn, 256, ATTN_SMEM>>>(bias2d);

    dim3 gout(DMODEL / 64, M_ROWS / 64);
    outproj_kernel<<<gout, 256>>>(wo, bo, out);
}

// round 2
// speedup vs baseline: 1.1222x; 1.1222x over previous
#include <cuda_runtime.h>
#include <math.h>

#define S_LEN  2048
#define BATCH  2
#define DMODEL 1024
#define NHEADS 16
#define HDIM   64
#define M_ROWS (S_LEN * BATCH)   // 4096

// Scratch (allocation-free)
__device__ float g_q[BATCH * NHEADS * S_LEN * HDIM];
__device__ float g_k[BATCH * NHEADS * S_LEN * HDIM];
__device__ float g_v[BATCH * NHEADS * S_LEN * HDIM];
__device__ float g_att[S_LEN * BATCH * DMODEL];

// ---------------------------------------------------------------------------
// fp32 GEMM: C[128x128] per block, 256 threads, 8x8 micro-tile, k-step 8,
// global->register prefetch. A [M,1024] row-major, W [1024,1024] row-major.
// ---------------------------------------------------------------------------
template <bool HEAD_OUT>
__device__ __forceinline__ void gemm_body(const float* __restrict__ A,
                                          const float* __restrict__ W,
                                          const float* __restrict__ bias,
                                          float* __restrict__ out)
{
    __shared__ float As[8][132];   // As[k][m] transposed
    __shared__ float Bs[8][132];   // Bs[k][n]

    const int tid = threadIdx.x;
    const int tx = tid & 15;       // 16 col groups
    const int ty = tid >> 4;       // 16 row groups (8 rows each)
    const int m0 = blockIdx.y * 128;
    const int n0 = blockIdx.x * 128;

    const int arow = tid >> 1;          // 0..127
    const int acol = (tid & 1) * 4;     // 0 or 4
    const int brow = tid >> 5;          // 0..7
    const int bcol = (tid & 31) * 4;    // 0..124

    const float* aPtr = A + (size_t)(m0 + arow) * DMODEL + acol;
    const float* bPtr = W + (size_t)brow * DMODEL + n0 + bcol;

    float4 ap = *(const float4*)aPtr;
    float4 bp = *(const float4*)bPtr;

    float acc[8][8];
#pragma unroll
    for (int i = 0; i < 8; i++)
#pragma unroll
        for (int j = 0; j < 8; j++) acc[i][j] = 0.f;

    for (int k0 = 0; k0 < DMODEL; k0 += 8) {
        As[acol + 0][arow] = ap.x;
        As[acol + 1][arow] = ap.y;
        As[acol + 2][arow] = ap.z;
        As[acol + 3][arow] = ap.w;
        *(float4*)&Bs[brow][bcol] = bp;
        __syncthreads();

        if (k0 + 8 < DMODEL) {
            ap = *(const float4*)(aPtr + k0 + 8);
            bp = *(const float4*)(bPtr + (size_t)(k0 + 8) * DMODEL);
        }

#pragma unroll
        for (int kk = 0; kk < 8; kk++) {
            float4 a0 = *(const float4*)&As[kk][ty * 8];
            float4 a1 = *(const float4*)&As[kk][ty * 8 + 4];
            float4 b0 = *(const float4*)&Bs[kk][tx * 4];
            float4 b1 = *(const float4*)&Bs[kk][64 + tx * 4];
            float ar[8] = {a0.x, a0.y, a0.z, a0.w, a1.x, a1.y, a1.z, a1.w};
            float br[8] = {b0.x, b0.y, b0.z, b0.w, b1.x, b1.y, b1.z, b1.w};
#pragma unroll
            for (int i = 0; i < 8; i++)
#pragma unroll
                for (int j = 0; j < 8; j++)
                    acc[i][j] = fmaf(ar[i], br[j], acc[i][j]);
        }
        __syncthreads();
    }

#pragma unroll
    for (int i = 0; i < 8; i++) {
        const int r = m0 + ty * 8 + i;
#pragma unroll
        for (int j2 = 0; j2 < 2; j2++) {
            const int c = n0 + j2 * 64 + tx * 4;   // 4 consecutive cols
            float4 v;
            v.x = acc[i][j2 * 4 + 0] + bias[c + 0];
            v.y = acc[i][j2 * 4 + 1] + bias[c + 1];
            v.z = acc[i][j2 * 4 + 2] + bias[c + 2];
            v.w = acc[i][j2 * 4 + 3] + bias[c + 3];
            if (HEAD_OUT) {
                const int s = r >> 1, b = r & 1;
                const int h = c >> 6, d = c & 63;
                *(float4*)&out[((((size_t)b * NHEADS + h) * S_LEN) + s) * HDIM + d] = v;
            } else {
                *(float4*)&out[(size_t)r * DMODEL + c] = v;
            }
        }
    }
}

__global__ __launch_bounds__(256, 2)
void qkv_kernel(const float* __restrict__ src,
                const float* __restrict__ wq, const float* __restrict__ bq,
                const float* __restrict__ wk, const float* __restrict__ bk,
                const float* __restrict__ wv, const float* __restrict__ bv)
{
    const float* W; const float* bs; float* out;
    if (blockIdx.z == 0)      { W = wq; bs = bq; out = g_q; }
    else if (blockIdx.z == 1) { W = wk; bs = bk; out = g_k; }
    else                      { W = wv; bs = bv; out = g_v; }
    gemm_body<true>(src, W, bs, out);
}

__global__ __launch_bounds__(256, 2)
void outproj_kernel(const float* __restrict__ wo, const float* __restrict__ bo,
                    float* __restrict__ out)
{
    gemm_body<false>(g_att, wo, bo, out);
}

// ---------------------------------------------------------------------------
// Flash attention, 128 queries x 64 keys per block, 256 threads, 8x4 micro.
//   logits = (q.k)*0.125 + bias[s,t];  attn = softmax(logits)*sign(bias)
// Shared: Qs[d][m] 64x132, Ks[d][n] 64x68, Vs[kc][hd] 64x68, Ps[m][kc] 128x68
// ---------------------------------------------------------------------------
#define Q_PAD 132
#define K_PAD 68
#define OFF_K (64 * Q_PAD)
#define OFF_V (OFF_K + 64 * K_PAD)
#define OFF_P (OFF_V + 64 * K_PAD)
#define ATTN_SMEM ((OFF_P + 128 * K_PAD) * 4)

__global__ __launch_bounds__(256, 2)
void attn_kernel(const float* __restrict__ bias2d)
{
    extern __shared__ float sm[];
    float* Qs = sm;
    float* Ks = sm + OFF_K;
    float* Vs = sm + OFF_V;
    float* Ps = sm + OFF_P;

    const int bh = blockIdx.y;            // 0..31
    const int b = bh >> 4, h = bh & 15;
    const int q0 = blockIdx.x * 128;
    const int tid = threadIdx.x;
    const int tx = tid & 15, ty = tid >> 4;

    const float* qb = g_q + (size_t)(b * NHEADS + h) * S_LEN * HDIM;
    const float* kb = g_k + (size_t)(b * NHEADS + h) * S_LEN * HDIM;
    const float* vb = g_v + (size_t)(b * NHEADS + h) * S_LEN * HDIM;

    const int lr = tid >> 4;          // 0..15
    const int lc = (tid & 15) * 4;    // 0..60

    // Q tile (128 x 64) -> d-major
#pragma unroll
    for (int p = 0; p < 8; p++) {
        const int r = lr + p * 16;
        float4 qv = *(const float4*)&qb[(size_t)(q0 + r) * HDIM + lc];
        Qs[(lc + 0) * Q_PAD + r] = qv.x;
        Qs[(lc + 1) * Q_PAD + r] = qv.y;
        Qs[(lc + 2) * Q_PAD + r] = qv.z;
        Qs[(lc + 3) * Q_PAD + r] = qv.w;
    }

    float mI[8], lI[8], O[8][4];
#pragma unroll
    for (int i = 0; i < 8; i++) {
        mI[i] = -INFINITY; lI[i] = 0.f;
#pragma unroll
        for (int j = 0; j < 4; j++) O[i][j] = 0.f;
    }

    for (int k0 = 0; k0 < S_LEN; k0 += 64) {
        __syncthreads();   // protect Ks/Vs/Ps from previous iteration readers
#pragma unroll
        for (int p = 0; p < 4; p++) {
            const int r = lr + p * 16;    // 0..63
            float4 kv = *(const float4*)&kb[(size_t)(k0 + r) * HDIM + lc];
            Ks[(lc + 0) * K_PAD + r] = kv.x;
            Ks[(lc + 1) * K_PAD + r] = kv.y;
            Ks[(lc + 2) * K_PAD + r] = kv.z;
            Ks[(lc + 3) * K_PAD + r] = kv.w;
            *(float4*)&Vs[r * K_PAD + lc] = *(const float4*)&vb[(size_t)(k0 + r) * HDIM + lc];
        }
        __syncthreads();

        // S tile: sv[i][j] = q[ty*8+i] . k[tx*4+j]
        float sv[8][4];
#pragma unroll
        for (int i = 0; i < 8; i++)
#pragma unroll
            for (int j = 0; j < 4; j++) sv[i][j] = 0.f;

#pragma unroll
        for (int d = 0; d < 64; d++) {
            float4 a0 = *(const float4*)&Qs[d * Q_PAD + ty * 8];
            float4 a1 = *(const float4*)&Qs[d * Q_PAD + ty * 8 + 4];
            float4 kv = *(const float4*)&Ks[d * K_PAD + tx * 4];
            float qr[8] = {a0.x, a0.y, a0.z, a0.w, a1.x, a1.y, a1.z, a1.w};
            float kr[4] = {kv.x, kv.y, kv.z, kv.w};
#pragma unroll
            for (int i = 0; i < 8; i++)
#pragma unroll
                for (int j = 0; j < 4; j++)
                    sv[i][j] = fmaf(qr[i], kr[j], sv[i][j]);
        }

        // scale + bias + sign + online softmax; write signed P
        unsigned sgn = 0;
#pragma unroll
        for (int i = 0; i < 8; i++) {
            float4 bb = *(const float4*)&bias2d[(size_t)(q0 + ty * 8 + i) * S_LEN + k0 + tx * 4];
            float bz[4] = {bb.x, bb.y, bb.z, bb.w};
            float rmax = -INFINITY;
#pragma unroll
            for (int j = 0; j < 4; j++) {
                float lg = fmaf(sv[i][j], 0.125f, bz[j]);
                sv[i][j] = lg;
                if (bz[j] < 0.f) sgn |= 1u << (i * 4 + j);
                rmax = fmaxf(rmax, lg);
            }
#pragma unroll
            for (int msk = 8; msk >= 1; msk >>= 1)
                rmax = fmaxf(rmax, __shfl_xor_sync(0xffffffffu, rmax, msk));
            const float mn = fmaxf(mI[i], rmax);
            const float al = __expf(mI[i] - mn);
            mI[i] = mn;
            lI[i] *= al;
#pragma unroll
            for (int j = 0; j < 4; j++) O[i][j] *= al;
            float4 pv;
            float e0 = __expf(sv[i][0] - mn);
            float e1 = __expf(sv[i][1] - mn);
            float e2 = __expf(sv[i][2] - mn);
            float e3 = __expf(sv[i][3] - mn);
            lI[i] += e0 + e1 + e2 + e3;
            pv.x = ((sgn >> (i * 4 + 0)) & 1u) ? -e0 : e0;
            pv.y = ((sgn >> (i * 4 + 1)) & 1u) ? -e1 : e1;
            pv.z = ((sgn >> (i * 4 + 2)) & 1u) ? -e2 : e2;
            pv.w = ((sgn >> (i * 4 + 3)) & 1u) ? -e3 : e3;
            *(float4*)&Ps[(ty * 8 + i) * K_PAD + tx * 4] = pv;
        }
        __syncthreads();

        // O += P @ V
#pragma unroll 4
        for (int kc = 0; kc < 64; kc++) {
            float pr[8];
#pragma unroll
            for (int i = 0; i < 8; i++) pr[i] = Ps[(ty * 8 + i) * K_PAD + kc];
            float4 vv = *(const float4*)&Vs[kc * K_PAD + tx * 4];
            float vr[4] = {vv.x, vv.y, vv.z, vv.w};
#pragma unroll
            for (int i = 0; i < 8; i++)
#pragma unroll
                for (int j = 0; j < 4; j++)
                    O[i][j] = fmaf(pr[i], vr[j], O[i][j]);
        }
    }

    // finalize
#pragma unroll
    for (int i = 0; i < 8; i++) {
        float l = lI[i];
#pragma unroll
        for (int msk = 8; msk >= 1; msk >>= 1)
            l += __shfl_xor_sync(0xffffffffu, l, msk);
        const float inv = 1.f / l;
        const int srow = q0 + ty * 8 + i;
        float4 o4 = make_float4(O[i][0] * inv, O[i][1] * inv,
                                O[i][2] * inv, O[i][3] * inv);
        *(float4*)&g_att[(size_t)(srow * BATCH + b) * DMODEL + h * HDIM + tx * 4] = o4;
    }
}

// ---------------------------------------------------------------------------
extern "C" void kernel_launch(void* const* d_in, const int* in_sizes, int n_in,
                              void* d_out, int out_size)
{
    const float* src    = (const float*)d_in[0];
    const float* bias2d = (const float*)d_in[1];
    const float* wq = (const float*)d_in[2];
    const float* bq = (const float*)d_in[3];
    const float* wk = (const float*)d_in[4];
    const float* bk = (const float*)d_in[5];
    const float* wv = (const float*)d_in[6];
    const float* bv = (const float*)d_in[7];
    const float* wo = (const float*)d_in[8];
    const float* bo = (const float*)d_in[9];
    float* out = (float*)d_out;

    cudaFuncSetAttribute(attn_kernel,
                         cudaFuncAttributeMaxDynamicSharedMemorySize, ATTN_SMEM);

    dim3 gproj(DMODEL / 128, M_ROWS / 128, 3);
    qkv_kernel<<<gproj, 256>>>(src, wq, bq, wk, bk, wv, bv);

    dim3 gattn(S_LEN / 128, BATCH * NHEADS);
    attn_kernel<<<gattn, 256, ATTN_SMEM>>>(bias2d);

    dim3 gout(DMODEL / 128, M_ROWS / 128);
    outproj_kernel<<<gout, 256>>>(wo, bo, out);
}

// round 4
// speedup vs baseline: 1.6351x; 1.4570x over previous
#include <cuda_runtime.h>
#include <cuda_bf16.h>
#include <math.h>
#include <stdint.h>

#define S_LEN  2048
#define BATCH  2
#define DMODEL 1024
#define NHEADS 16
#define HDIM   64
#define M_ROWS 4096

typedef __nv_bfloat16 bf16;

// Arch-specific (tcgen05-capable) compilation pass?
#if defined(__CUDA_ARCH__) && (defined(__CUDA_ARCH_SPECIFIC__) || \
    defined(__CUDA_ARCH_FEAT_SM103_ALL) || defined(__CUDA_ARCH_FEAT_SM100_ALL))
#define TC_OK 1
#else
#define TC_OK 0
#endif

// ------------------------------ scratch ------------------------------------
__device__ float g_q[M_ROWS * DMODEL];      // [m][c],  m = s*BATCH + b
__device__ float g_k[M_ROWS * DMODEL];
__device__ float g_v[M_ROWS * DMODEL];
__device__ float g_att[M_ROWS * DMODEL];

__device__ bf16 g_srchi[M_ROWS * DMODEL];
__device__ bf16 g_srclo[M_ROWS * DMODEL];
__device__ bf16 g_atthi[M_ROWS * DMODEL];
__device__ bf16 g_attlo[M_ROWS * DMODEL];
__device__ bf16 g_whi[4][DMODEL * DMODEL];  // W^T [n][k], bf16 hi
__device__ bf16 g_wlo[4][DMODEL * DMODEL];  // W^T [n][k], bf16 lo

// ------------------------------ generic helpers ----------------------------
__device__ __forceinline__ uint32_t smem_u32(const void* p) {
    uint32_t a;
    asm("{ .reg .u64 t; cvta.to.shared.u64 t, %1; cvt.u32.u64 %0, t; }"
        : "=r"(a) : "l"(p));
    return a;
}
__device__ __forceinline__ void cp16(uint32_t s, const void* g) {
    asm volatile("cp.async.cg.shared.global [%0], [%1], 16;" :: "r"(s), "l"(g));
}
#define CP_COMMIT() asm volatile("cp.async.commit_group;" ::: "memory")
#define CP_WAIT0()  asm volatile("cp.async.wait_group 0;" ::: "memory")
#define MBARRIER_INIT(mb, c) \
    asm volatile("mbarrier.init.shared.b64 [%0], %1;" :: "r"((uint32_t)(mb)), "r"((uint32_t)(c)) : "memory")
#define MBAR_WAIT(mb, par) do {                                                  \
    uint32_t _m = (uint32_t)(mb); uint32_t _p = (uint32_t)(par); uint32_t _d;    \
    asm volatile("{\n\t.reg .pred p;\n\t"                                        \
        "mbarrier.try_wait.parity.acquire.cta.shared::cta.b64 p, [%1], %2;\n\t"  \
        "selp.b32 %0, 1, 0, p;\n\t}" : "=r"(_d) : "r"(_m), "r"(_p) : "memory");  \
    if (!_d) {                                                                   \
        asm volatile("{\n\t.reg .pred P1;\n\tWL_%=:\n\t"                         \
            "mbarrier.try_wait.parity.acquire.cta.shared::cta.b64 P1, [%0], %1, 0x989680;\n\t" \
            "@P1 bra.uni WD_%=;\n\tbra.uni WL_%=;\n\tWD_%=:\n\t}"                \
            :: "r"(_m), "r"(_p) : "memory");                                     \
    } } while (0)

#if TC_OK
// --------------------------- tcgen05 wrappers ------------------------------
__device__ __forceinline__ uint32_t elect_one() {
    uint32_t pred;
    asm volatile("{\n\t.reg .pred p;\n\telect.sync _|p, 0xFFFFFFFF;\n\t"
                 "selp.b32 %0, 1, 0, p;\n\t}" : "=r"(pred));
    return pred;
}
#define TCGEN05_ALLOC(sa, n) \
    asm volatile("tcgen05.alloc.cta_group::1.sync.aligned.shared::cta.b32 [%0], %1;" \
                 :: "r"((uint32_t)(sa)), "r"((uint32_t)(n)) : "memory")
#define TCGEN05_DEALLOC(t, n) \
    asm volatile("tcgen05.dealloc.cta_group::1.sync.aligned.b32 %0, %1;" :: "r"(t), "r"((uint32_t)(n)))
#define TCGEN05_RELINQ() \
    asm volatile("tcgen05.relinquish_alloc_permit.cta_group::1.sync.aligned;")
#define TCGEN05_COMMIT(mb) \
    asm volatile("tcgen05.commit.cta_group::1.mbarrier::arrive::one.shared::cluster.b64 [%0];" \
                 :: "r"((uint32_t)(mb)) : "memory")
#define TCGEN05_FENCE_AFTER()  asm volatile("tcgen05.fence::after_thread_sync;" ::: "memory")
#define TCGEN05_FENCE_BEFORE() asm volatile("tcgen05.fence::before_thread_sync;" ::: "memory")
#define TCGEN05_WAIT_LD()      asm volatile("tcgen05.wait::ld.sync.aligned;" ::: "memory")
#define TCGEN05_LD_X32(r, ta) \
    asm volatile("tcgen05.ld.sync.aligned.32x32b.x32.b32 " \
        "{%0,%1,%2,%3,%4,%5,%6,%7,%8,%9,%10,%11,%12,%13,%14,%15," \
        "%16,%17,%18,%19,%20,%21,%22,%23,%24,%25,%26,%27,%28,%29,%30,%31}, [%32];" \
        : "=r"((r)[0]),"=r"((r)[1]),"=r"((r)[2]),"=r"((r)[3]),"=r"((r)[4]),"=r"((r)[5]),"=r"((r)[6]),"=r"((r)[7]), \
          "=r"((r)[8]),"=r"((r)[9]),"=r"((r)[10]),"=r"((r)[11]),"=r"((r)[12]),"=r"((r)[13]),"=r"((r)[14]),"=r"((r)[15]), \
          "=r"((r)[16]),"=r"((r)[17]),"=r"((r)[18]),"=r"((r)[19]),"=r"((r)[20]),"=r"((r)[21]),"=r"((r)[22]),"=r"((r)[23]), \
          "=r"((r)[24]),"=r"((r)[25]),"=r"((r)[26]),"=r"((r)[27]),"=r"((r)[28]),"=r"((r)[29]),"=r"((r)[30]),"=r"((r)[31]) \
        : "r"(ta))

static __device__ __forceinline__ uint64_t make_desc_sw128(uint32_t base) {
    const uint64_t B = (uint64_t(2) << 61) | (uint64_t(1) << 46)
                     | (uint64_t(64) << 32) | (uint64_t(1) << 16);
    return B | ((uint64_t)(base >> 4) & 0x3FFF);
}
__device__ __forceinline__ void mma_f16_ss(uint32_t d, uint64_t a, uint64_t b,
                                           uint32_t idesc, uint32_t en) {
    asm volatile("{\n\t.reg .pred p;\n\tsetp.ne.u32 p, %5, 0;\n\t"
        "tcgen05.mma.cta_group::1.kind::f16 [%0], %1, %2, %3, {%4,%4,%4,%4}, p;\n\t}"
        :: "r"(d), "l"(a), "l"(b), "r"(idesc), "r"(0u), "r"(en) : "memory");
}
#endif // TC_OK

// ------------------------------ prep kernels -------------------------------
__global__ void split_kernel(const float* __restrict__ in,
                             bf16* __restrict__ hi, bf16* __restrict__ lo)
{
    int i = blockIdx.x * blockDim.x + threadIdx.x;       // float4 index
    float4 x = ((const float4*)in)[i];
    bf16 h0 = __float2bfloat16_rn(x.x), h1 = __float2bfloat16_rn(x.y);
    bf16 h2 = __float2bfloat16_rn(x.z), h3 = __float2bfloat16_rn(x.w);
    __nv_bfloat162 H0; H0.x = h0; H0.y = h1;
    __nv_bfloat162 H1; H1.x = h2; H1.y = h3;
    __nv_bfloat162 L0, L1;
    L0.x = __float2bfloat16_rn(x.x - __bfloat162float(h0));
    L0.y = __float2bfloat16_rn(x.y - __bfloat162float(h1));
    L1.x = __float2bfloat16_rn(x.z - __bfloat162float(h2));
    L1.y = __float2bfloat16_rn(x.w - __bfloat162float(h3));
    ((__nv_bfloat162*)hi)[i * 2] = H0; ((__nv_bfloat162*)hi)[i * 2 + 1] = H1;
    ((__nv_bfloat162*)lo)[i * 2] = L0; ((__nv_bfloat162*)lo)[i * 2 + 1] = L1;
}

__global__ void wprep_kernel(const float* __restrict__ w0, const float* __restrict__ w1,
                             const float* __restrict__ w2, const float* __restrict__ w3)
{
    __shared__ float t[32][33];
    const float* W = (blockIdx.z == 0) ? w0 : (blockIdx.z == 1) ? w1
                   : (blockIdx.z == 2) ? w2 : w3;
    bf16* Whi = g_whi[blockIdx.z];
    bf16* Wlo = g_wlo[blockIdx.z];
    const int n0 = blockIdx.x * 32, k0 = blockIdx.y * 32;
    const int tx = threadIdx.x, ty = threadIdx.y;
#pragma unroll
    for (int i = 0; i < 4; i++)
        t[ty + i * 8][tx] = W[(size_t)(k0 + ty + i * 8) * DMODEL + n0 + tx];
    __syncthreads();
#pragma unroll
    for (int i = 0; i < 4; i++) {
        const int n = n0 + ty + i * 8, k = k0 + tx;
        float v = t[tx][ty + i * 8];
        bf16 h = __float2bfloat16_rn(v);
        Whi[(size_t)n * DMODEL + k] = h;
        Wlo[(size_t)n * DMODEL + k] = __float2bfloat16_rn(v - __bfloat162float(h));
    }
}

// ------------------------------ tcgen05 GEMM -------------------------------
// C[128x128] per CTA; K-chunks of 64 bf16; SS-mode MMA, 3-product bf16 split.
#define GT_M 128
#define GT_N 128
#define GT_K 64
#define NCHUNK (DMODEL / GT_K)            // 16
#define TILE_B (GT_M * GT_K * 2)          // 16384 bytes
#define STAGE_B (4 * TILE_B)              // 64 KB
#define GEMM_SMEM (2 * STAGE_B + 1024)
// idesc: F32 accum, bf16 a/b, N=128, M=128
#define GT_IDESC ((1u<<4)|(1u<<7)|(1u<<10)|((GT_N/8)<<17)|((GT_M/16)<<24))

#if TC_OK
__device__ __forceinline__ void load_chunk(uint32_t sbase,
    const bf16* __restrict__ Ah, const bf16* __restrict__ Al,
    const bf16* __restrict__ Bh, const bf16* __restrict__ Bl,
    int m0, int n0, int kc, int tid)
{
    const bf16* srcs[4] = { Ah, Al, Bh, Bl };
    const int rb[4] = { m0, m0, n0, n0 };
#pragma unroll
    for (int t = 0; t < 4; t++) {
#pragma unroll
        for (int p = 0; p < 4; p++) {
            const int u = p * 256 + tid;           // 16B line index (0..1023)
            const int row = u >> 3, col = u & 7;
            const void* g = srcs[t] + (size_t)(rb[t] + row) * DMODEL + kc * GT_K + col * 8;
            const uint32_t off = (uint32_t)(u * 16);
            cp16(sbase + t * TILE_B + (off ^ ((off >> 3) & 0x70)), g);
        }
    }
}
#endif

__global__ __launch_bounds__(256, 1)
void gemm_tc_kernel(const bf16* __restrict__ Ah, const bf16* __restrict__ Al,
                    int wsel, const float* __restrict__ bias,
                    float* __restrict__ out)
{
#if TC_OK
    extern __shared__ char dyn[];
    __shared__ uint32_t s_tmem;
    __shared__ uint64_t s_mbar[2];

    const int tid = threadIdx.x, wid = tid >> 5, lid = tid & 31;
    const int n0 = blockIdx.x * GT_N, m0 = blockIdx.y * GT_M;
    const bf16* Bh = g_whi[wsel];
    const bf16* Bl = g_wlo[wsel];

    uint32_t base = smem_u32(dyn);
    base = (base + 1023u) & ~1023u;
    const uint32_t stg0 = base, stg1 = base + STAGE_B;
    const uint32_t mb0 = smem_u32(&s_mbar[0]), mb1 = smem_u32(&s_mbar[1]);

    if (wid == 0) { TCGEN05_ALLOC(smem_u32(&s_tmem), 128); TCGEN05_RELINQ(); }
    if (tid == 0) { MBARRIER_INIT(mb0, 1); MBARRIER_INIT(mb1, 1); }
    __syncthreads();
    const uint32_t tmem = s_tmem;

    load_chunk(stg0, Ah, Al, Bh, Bl, m0, n0, 0, tid);
    CP_COMMIT();

    uint32_t pc0 = 0, pc1 = 0;
    for (int c = 0; c < NCHUNK; c++) {
        const uint32_t ss = (c & 1) ? stg1 : stg0;
        CP_WAIT0();
        __syncthreads();
        if (wid == 0) {
            const uint64_t dAh = make_desc_sw128(ss);
            const uint64_t dAl = make_desc_sw128(ss + TILE_B);
            const uint64_t dBh = make_desc_sw128(ss + 2 * TILE_B);
            const uint64_t dBl = make_desc_sw128(ss + 3 * TILE_B);
            if (elect_one()) {
                asm volatile("fence.proxy.async.shared::cta;" ::: "memory");
#pragma unroll
                for (int ks = 0; ks < 4; ks++)
                    mma_f16_ss(tmem, dAh + ks * 2, dBh + ks * 2, GT_IDESC,
                               (c == 0 && ks == 0) ? 0u : 1u);
#pragma unroll
                for (int ks = 0; ks < 4; ks++)
                    mma_f16_ss(tmem, dAh + ks * 2, dBl + ks * 2, GT_IDESC, 1u);
#pragma unroll
                for (int ks = 0; ks < 4; ks++)
                    mma_f16_ss(tmem, dAl + ks * 2, dBh + ks * 2, GT_IDESC, 1u);
                TCGEN05_COMMIT((c & 1) ? mb1 : mb0);
            }
        }
        if (c + 1 < NCHUNK) {
            if (c >= 1) {            // wait: MMAs of chunk c-1 done with that stage
                if ((c + 1) & 1) { MBAR_WAIT(mb1, pc1); pc1 ^= 1; }
                else             { MBAR_WAIT(mb0, pc0); pc0 ^= 1; }
            }
            load_chunk((c + 1) & 1 ? stg1 : stg0, Ah, Al, Bh, Bl, m0, n0, c + 1, tid);
            CP_COMMIT();
        }
    }
    MBAR_WAIT(mb0, pc0);
    MBAR_WAIT(mb1, pc1);
    TCGEN05_FENCE_AFTER();

    if (wid < 4) {                    // epilogue: 128 rows x 128 cols
        const int m = m0 + wid * 32 + lid;
#pragma unroll
        for (int g = 0; g < 4; g++) {
            uint32_t r[32];
            TCGEN05_LD_X32(r, tmem + g * 32);
            TCGEN05_WAIT_LD();
            const int cb = n0 + g * 32;
#pragma unroll
            for (int q = 0; q < 8; q++) {
                float4 v;
                v.x = __uint_as_float(r[q * 4 + 0]) + bias[cb + q * 4 + 0];
                v.y = __uint_as_float(r[q * 4 + 1]) + bias[cb + q * 4 + 1];
                v.z = __uint_as_float(r[q * 4 + 2]) + bias[cb + q * 4 + 2];
                v.w = __uint_as_float(r[q * 4 + 3]) + bias[cb + q * 4 + 3];
                *(float4*)&out[(size_t)m * DMODEL + cb + q * 4] = v;
            }
        }
        TCGEN05_FENCE_BEFORE();
    }
    __syncthreads();
    if (wid == 0) TCGEN05_DEALLOC(tmem, 128);
#else
    // Fallback body for the generic (compute_103) PTX pass. Never executed on
    // the GB300 (the sm_103a cubin is exact-match), but must be correct.
    const int tid = threadIdx.x;
    const int n0 = blockIdx.x * GT_N, m0 = blockIdx.y * GT_M;
    const bf16* Bh = g_whi[wsel];
    const bf16* Bl = g_wlo[wsel];
    for (int idx = tid; idx < GT_M * GT_N; idx += 256) {
        const int m = m0 + idx / GT_N, n = n0 + idx % GT_N;
        float s = bias[n];
        for (int k = 0; k < DMODEL; k++) {
            float a = __bfloat162float(Ah[(size_t)m * DMODEL + k]) +
                      __bfloat162float(Al[(size_t)m * DMODEL + k]);
            float b = __bfloat162float(Bh[(size_t)n * DMODEL + k]) +
                      __bfloat162float(Bl[(size_t)n * DMODEL + k]);
            s = fmaf(a, b, s);
        }
        out[(size_t)m * DMODEL + n] = s;
    }
#endif
}

// ------------------------------ attention (SIMT fp32) ----------------------
#define Q_PAD 132
#define K_PAD 68
#define OFF_K (64 * Q_PAD)
#define OFF_V (OFF_K + 64 * K_PAD)
#define OFF_P (OFF_V + 64 * K_PAD)
#define ATTN_SMEM ((OFF_P + 128 * K_PAD) * 4)

__global__ __launch_bounds__(256, 2)
void attn_kernel(const float* __restrict__ bias2d)
{
    extern __shared__ float sm[];
    float* Qs = sm;
    float* Ks = sm + OFF_K;
    float* Vs = sm + OFF_V;
    float* Ps = sm + OFF_P;

    const int bh = blockIdx.y;
    const int b = bh >> 4, h = bh & 15;
    const int q0 = blockIdx.x * 128;
    const int tid = threadIdx.x;
    const int tx = tid & 15, ty = tid >> 4;
    const int lr = tid >> 4, lc = (tid & 15) * 4;
    const int hc = h * HDIM;

#pragma unroll
    for (int p = 0; p < 8; p++) {
        const int r = lr + p * 16;
        float4 qv = *(const float4*)&g_q[(size_t)((q0 + r) * 2 + b) * DMODEL + hc + lc];
        Qs[(lc + 0) * Q_PAD + r] = qv.x;
        Qs[(lc + 1) * Q_PAD + r] = qv.y;
        Qs[(lc + 2) * Q_PAD + r] = qv.z;
        Qs[(lc + 3) * Q_PAD + r] = qv.w;
    }

    float mI[8], lI[8], O[8][4];
#pragma unroll
    for (int i = 0; i < 8; i++) {
        mI[i] = -INFINITY; lI[i] = 0.f;
#pragma unroll
        for (int j = 0; j < 4; j++) O[i][j] = 0.f;
    }

    for (int k0 = 0; k0 < S_LEN; k0 += 64) {
        __syncthreads();
#pragma unroll
        for (int p = 0; p < 4; p++) {
            const int r = lr + p * 16;
            float4 kv = *(const float4*)&g_k[(size_t)((k0 + r) * 2 + b) * DMODEL + hc + lc];
            Ks[(lc + 0) * K_PAD + r] = kv.x;
            Ks[(lc + 1) * K_PAD + r] = kv.y;
            Ks[(lc + 2) * K_PAD + r] = kv.z;
            Ks[(lc + 3) * K_PAD + r] = kv.w;
            *(float4*)&Vs[r * K_PAD + lc] =
                *(const float4*)&g_v[(size_t)((k0 + r) * 2 + b) * DMODEL + hc + lc];
        }
        __syncthreads();

        float sv[8][4];
#pragma unroll
        for (int i = 0; i < 8; i++)
#pragma unroll
            for (int j = 0; j < 4; j++) sv[i][j] = 0.f;
#pragma unroll
        for (int d = 0; d < 64; d++) {
            float4 a0 = *(const float4*)&Qs[d * Q_PAD + ty * 8];
            float4 a1 = *(const float4*)&Qs[d * Q_PAD + ty * 8 + 4];
            float4 kv = *(const float4*)&Ks[d * K_PAD + tx * 4];
            float qr[8] = {a0.x, a0.y, a0.z, a0.w, a1.x, a1.y, a1.z, a1.w};
            float kr[4] = {kv.x, kv.y, kv.z, kv.w};
#pragma unroll
            for (int i = 0; i < 8; i++)
#pragma unroll
                for (int j = 0; j < 4; j++)
                    sv[i][j] = fmaf(qr[i], kr[j], sv[i][j]);
        }

        unsigned sgn = 0;
#pragma unroll
        for (int i = 0; i < 8; i++) {
            float4 bb = *(const float4*)&bias2d[(size_t)(q0 + ty * 8 + i) * S_LEN + k0 + tx * 4];
            float bz[4] = {bb.x, bb.y, bb.z, bb.w};
            float rmax = -INFINITY;
#pragma unroll
            for (int j = 0; j < 4; j++) {
                float lg = fmaf(sv[i][j], 0.125f, bz[j]);
                sv[i][j] = lg;
                if (bz[j] < 0.f) sgn |= 1u << (i * 4 + j);
                rmax = fmaxf(rmax, lg);
            }
#pragma unroll
            for (int msk = 8; msk >= 1; msk >>= 1)
                rmax = fmaxf(rmax, __shfl_xor_sync(0xffffffffu, rmax, msk));
            const float mn = fmaxf(mI[i], rmax);
            const float al = __expf(mI[i] - mn);
            mI[i] = mn;
            lI[i] *= al;
#pragma unroll
            for (int j = 0; j < 4; j++) O[i][j] *= al;
            float e0 = __expf(sv[i][0] - mn);
            float e1 = __expf(sv[i][1] - mn);
            float e2 = __expf(sv[i][2] - mn);
            float e3 = __expf(sv[i][3] - mn);
            lI[i] += e0 + e1 + e2 + e3;
            float4 pv;
            pv.x = ((sgn >> (i * 4 + 0)) & 1u) ? -e0 : e0;
            pv.y = ((sgn >> (i * 4 + 1)) & 1u) ? -e1 : e1;
            pv.z = ((sgn >> (i * 4 + 2)) & 1u) ? -e2 : e2;
            pv.w = ((sgn >> (i * 4 + 3)) & 1u) ? -e3 : e3;
            *(float4*)&Ps[(ty * 8 + i) * K_PAD + tx * 4] = pv;
        }
        __syncthreads();

#pragma unroll 4
        for (int kc = 0; kc < 64; kc++) {
            float pr[8];
#pragma unroll
            for (int i = 0; i < 8; i++) pr[i] = Ps[(ty * 8 + i) * K_PAD + kc];
            float4 vv = *(const float4*)&Vs[kc * K_PAD + tx * 4];
            float vr[4] = {vv.x, vv.y, vv.z, vv.w};
#pragma unroll
            for (int i = 0; i < 8; i++)
#pragma unroll
                for (int j = 0; j < 4; j++)
                    O[i][j] = fmaf(pr[i], vr[j], O[i][j]);
        }
    }

#pragma unroll
    for (int i = 0; i < 8; i++) {
        float l = lI[i];
#pragma unroll
        for (int msk = 8; msk >= 1; msk >>= 1)
            l += __shfl_xor_sync(0xffffffffu, l, msk);
        const float inv = 1.f / l;
        const int srow = q0 + ty * 8 + i;
        float4 o4 = make_float4(O[i][0] * inv, O[i][1] * inv,
                                O[i][2] * inv, O[i][3] * inv);
        *(float4*)&g_att[(size_t)(srow * 2 + b) * DMODEL + hc + tx * 4] = o4;
    }
}

// ------------------------------ launch -------------------------------------
extern "C" void kernel_launch(void* const* d_in, const int* in_sizes, int n_in,
                              void* d_out, int out_size)
{
    const float* src    = (const float*)d_in[0];
    const float* bias2d = (const float*)d_in[1];
    const float* wq = (const float*)d_in[2];
    const float* bq = (const float*)d_in[3];
    const float* wk = (const float*)d_in[4];
    const float* bk = (const float*)d_in[5];
    const float* wv = (const float*)d_in[6];
    const float* bv = (const float*)d_in[7];
    const float* wo = (const float*)d_in[8];
    const float* bo = (const float*)d_in[9];
    float* out = (float*)d_out;

    cudaFuncSetAttribute(attn_kernel,
                         cudaFuncAttributeMaxDynamicSharedMemorySize, ATTN_SMEM);
    cudaFuncSetAttribute(gemm_tc_kernel,
                         cudaFuncAttributeMaxDynamicSharedMemorySize, GEMM_SMEM);

    bf16 *srchi, *srclo, *atthi, *attlo;
    float *gatt, *gq, *gk, *gv;
    cudaGetSymbolAddress((void**)&srchi, g_srchi);
    cudaGetSymbolAddress((void**)&srclo, g_srclo);
    cudaGetSymbolAddress((void**)&atthi, g_atthi);
    cudaGetSymbolAddress((void**)&attlo, g_attlo);
    cudaGetSymbolAddress((void**)&gatt, g_att);
    cudaGetSymbolAddress((void**)&gq, g_q);
    cudaGetSymbolAddress((void**)&gk, g_k);
    cudaGetSymbolAddress((void**)&gv, g_v);

    split_kernel<<<(M_ROWS * DMODEL / 4) / 256, 256>>>(src, srchi, srclo);
    wprep_kernel<<<dim3(32, 32, 4), dim3(32, 8)>>>(wq, wk, wv, wo);

    dim3 gg(DMODEL / GT_N, M_ROWS / GT_M);
    gemm_tc_kernel<<<gg, 256, GEMM_SMEM>>>(srchi, srclo, 0, bq, gq);
    gemm_tc_kernel<<<gg, 256, GEMM_SMEM>>>(srchi, srclo, 1, bk, gk);
    gemm_tc_kernel<<<gg, 256, GEMM_SMEM>>>(srchi, srclo, 2, bv, gv);

    dim3 gattn(S_LEN / 128, BATCH * NHEADS);
    attn_kernel<<<gattn, 256, ATTN_SMEM>>>(bias2d);

    split_kernel<<<(M_ROWS * DMODEL / 4) / 256, 256>>>(gatt, atthi, attlo);
    gemm_tc_kernel<<<gg, 256, GEMM_SMEM>>>(atthi, attlo, 3, bo, out);
}

// round 5
// speedup vs baseline: 2.9346x; 1.7948x over previous
#include <cuda_runtime.h>
#include <cuda_bf16.h>
#include <math.h>
#include <stdint.h>

#define S_LEN  2048
#define BATCH  2
#define DMODEL 1024
#define NHEADS 16
#define HDIM   64
#define M_ROWS 4096
#define NBH    (BATCH * NHEADS)

typedef __nv_bfloat16 bf16;

#if defined(__CUDA_ARCH__) && (defined(__CUDA_ARCH_SPECIFIC__) || \
    defined(__CUDA_ARCH_FEAT_SM103_ALL) || defined(__CUDA_ARCH_FEAT_SM100_ALL))
#define TC_OK 1
#else
#define TC_OK 0
#endif

// ------------------------------ scratch ------------------------------------
__device__ bf16 g_srchi[M_ROWS * DMODEL];
__device__ bf16 g_srclo[M_ROWS * DMODEL];
__device__ bf16 g_whi[4][DMODEL * DMODEL];   // W^T [n][k]
__device__ bf16 g_wlo[4][DMODEL * DMODEL];
__device__ bf16 g_qhi[NBH * S_LEN * HDIM];   // [bh][s][d]
__device__ bf16 g_qlo[NBH * S_LEN * HDIM];
__device__ bf16 g_khi[NBH * S_LEN * HDIM];
__device__ bf16 g_klo[NBH * S_LEN * HDIM];
__device__ float g_v[M_ROWS * DMODEL];       // fp32 [m][c]
__device__ bf16 g_vthi[NBH * HDIM * S_LEN];  // [bh][d][s]
__device__ bf16 g_vtlo[NBH * HDIM * S_LEN];
__device__ bf16 g_atthi[M_ROWS * DMODEL];    // [m][c]
__device__ bf16 g_attlo[M_ROWS * DMODEL];

// ------------------------------ helpers ------------------------------------
__device__ __forceinline__ uint32_t smem_u32(const void* p) {
    uint32_t a;
    asm("{ .reg .u64 t; cvta.to.shared.u64 t, %1; cvt.u32.u64 %0, t; }"
        : "=r"(a) : "l"(p));
    return a;
}
__device__ __forceinline__ void cp16(uint32_t s, const void* g) {
    asm volatile("cp.async.cg.shared.global [%0], [%1], 16;" :: "r"(s), "l"(g));
}
#define CP_COMMIT() asm volatile("cp.async.commit_group;" ::: "memory")
#define CP_WAIT0()  asm volatile("cp.async.wait_group 0;" ::: "memory")
#define MBARRIER_INIT(mb, c) \
    asm volatile("mbarrier.init.shared.b64 [%0], %1;" :: "r"((uint32_t)(mb)), "r"((uint32_t)(c)) : "memory")
#define MBAR_WAIT(mb, par) do {                                                  \
    uint32_t _m = (uint32_t)(mb); uint32_t _p = (uint32_t)(par); uint32_t _d;    \
    asm volatile("{\n\t.reg .pred p;\n\t"                                        \
        "mbarrier.try_wait.parity.acquire.cta.shared::cta.b64 p, [%1], %2;\n\t"  \
        "selp.b32 %0, 1, 0, p;\n\t}" : "=r"(_d) : "r"(_m), "r"(_p) : "memory");  \
    if (!_d) {                                                                   \
        asm volatile("{\n\t.reg .pred P1;\n\tWL_%=:\n\t"                         \
            "mbarrier.try_wait.parity.acquire.cta.shared::cta.b64 P1, [%0], %1, 0x989680;\n\t" \
            "@P1 bra.uni WD_%=;\n\tbra.uni WL_%=;\n\tWD_%=:\n\t}"                \
            :: "r"(_m), "r"(_p) : "memory");                                     \
    } } while (0)
__device__ __forceinline__ uint32_t swz(uint32_t off) {
    return off ^ ((off >> 3) & 0x70);
}

#if TC_OK
__device__ __forceinline__ uint32_t elect_one() {
    uint32_t pred;
    asm volatile("{\n\t.reg .pred p;\n\telect.sync _|p, 0xFFFFFFFF;\n\t"
                 "selp.b32 %0, 1, 0, p;\n\t}" : "=r"(pred));
    return pred;
}
#define TCGEN05_ALLOC(sa, n) \
    asm volatile("tcgen05.alloc.cta_group::1.sync.aligned.shared::cta.b32 [%0], %1;" \
                 :: "r"((uint32_t)(sa)), "r"((uint32_t)(n)) : "memory")
#define TCGEN05_DEALLOC(t, n) \
    asm volatile("tcgen05.dealloc.cta_group::1.sync.aligned.b32 %0, %1;" :: "r"(t), "r"((uint32_t)(n)))
#define TCGEN05_RELINQ() \
    asm volatile("tcgen05.relinquish_alloc_permit.cta_group::1.sync.aligned;")
#define TCGEN05_COMMIT(mb) \
    asm volatile("tcgen05.commit.cta_group::1.mbarrier::arrive::one.shared::cluster.b64 [%0];" \
                 :: "r"((uint32_t)(mb)) : "memory")
#define TCGEN05_FENCE_AFTER()  asm volatile("tcgen05.fence::after_thread_sync;" ::: "memory")
#define TCGEN05_FENCE_BEFORE() asm volatile("tcgen05.fence::before_thread_sync;" ::: "memory")
#define TCGEN05_WAIT_LD()      asm volatile("tcgen05.wait::ld.sync.aligned;" ::: "memory")
#define TCGEN05_LD_X32(r, ta) \
    asm volatile("tcgen05.ld.sync.aligned.32x32b.x32.b32 " \
        "{%0,%1,%2,%3,%4,%5,%6,%7,%8,%9,%10,%11,%12,%13,%14,%15," \
        "%16,%17,%18,%19,%20,%21,%22,%23,%24,%25,%26,%27,%28,%29,%30,%31}, [%32];" \
        : "=r"((r)[0]),"=r"((r)[1]),"=r"((r)[2]),"=r"((r)[3]),"=r"((r)[4]),"=r"((r)[5]),"=r"((r)[6]),"=r"((r)[7]), \
          "=r"((r)[8]),"=r"((r)[9]),"=r"((r)[10]),"=r"((r)[11]),"=r"((r)[12]),"=r"((r)[13]),"=r"((r)[14]),"=r"((r)[15]), \
          "=r"((r)[16]),"=r"((r)[17]),"=r"((r)[18]),"=r"((r)[19]),"=r"((r)[20]),"=r"((r)[21]),"=r"((r)[22]),"=r"((r)[23]), \
          "=r"((r)[24]),"=r"((r)[25]),"=r"((r)[26]),"=r"((r)[27]),"=r"((r)[28]),"=r"((r)[29]),"=r"((r)[30]),"=r"((r)[31]) \
        : "r"(ta))

static __device__ __forceinline__ uint64_t make_desc_sw128(uint32_t base) {
    const uint64_t B = (uint64_t(2) << 61) | (uint64_t(1) << 46)
                     | (uint64_t(64) << 32) | (uint64_t(1) << 16);
    return B | ((uint64_t)(base >> 4) & 0x3FFF);
}
__device__ __forceinline__ void mma_f16_ss(uint32_t d, uint64_t a, uint64_t b,
                                           uint32_t idesc, uint32_t en) {
    asm volatile("{\n\t.reg .pred p;\n\tsetp.ne.u32 p, %5, 0;\n\t"
        "tcgen05.mma.cta_group::1.kind::f16 [%0], %1, %2, %3, {%4,%4,%4,%4}, p;\n\t}"
        :: "r"(d), "l"(a), "l"(b), "r"(idesc), "r"(0u), "r"(en) : "memory");
}
#endif // TC_OK

// ------------------------------ prep kernels -------------------------------
__global__ void split_kernel(const float* __restrict__ in,
                             bf16* __restrict__ hi, bf16* __restrict__ lo)
{
    int i = blockIdx.x * blockDim.x + threadIdx.x;
    float4 x = ((const float4*)in)[i];
    bf16 h0 = __float2bfloat16_rn(x.x), h1 = __float2bfloat16_rn(x.y);
    bf16 h2 = __float2bfloat16_rn(x.z), h3 = __float2bfloat16_rn(x.w);
    __nv_bfloat162 H0; H0.x = h0; H0.y = h1;
    __nv_bfloat162 H1; H1.x = h2; H1.y = h3;
    __nv_bfloat162 L0, L1;
    L0.x = __float2bfloat16_rn(x.x - __bfloat162float(h0));
    L0.y = __float2bfloat16_rn(x.y - __bfloat162float(h1));
    L1.x = __float2bfloat16_rn(x.z - __bfloat162float(h2));
    L1.y = __float2bfloat16_rn(x.w - __bfloat162float(h3));
    ((__nv_bfloat162*)hi)[i * 2] = H0; ((__nv_bfloat162*)hi)[i * 2 + 1] = H1;
    ((__nv_bfloat162*)lo)[i * 2] = L0; ((__nv_bfloat162*)lo)[i * 2 + 1] = L1;
}

__global__ void wprep_kernel(const float* __restrict__ w0, const float* __restrict__ w1,
                             const float* __restrict__ w2, const float* __restrict__ w3)
{
    __shared__ float t[32][33];
    const float* W = (blockIdx.z == 0) ? w0 : (blockIdx.z == 1) ? w1
                   : (blockIdx.z == 2) ? w2 : w3;
    bf16* Whi = g_whi[blockIdx.z];
    bf16* Wlo = g_wlo[blockIdx.z];
    const int n0 = blockIdx.x * 32, k0 = blockIdx.y * 32;
    const int tx = threadIdx.x, ty = threadIdx.y;
#pragma unroll
    for (int i = 0; i < 4; i++)
        t[ty + i * 8][tx] = W[(size_t)(k0 + ty + i * 8) * DMODEL + n0 + tx];
    __syncthreads();
#pragma unroll
    for (int i = 0; i < 4; i++) {
        const int n = n0 + ty + i * 8, k = k0 + tx;
        float v = t[tx][ty + i * 8];
        bf16 h = __float2bfloat16_rn(v);
        Whi[(size_t)n * DMODEL + k] = h;
        Wlo[(size_t)n * DMODEL + k] = __float2bfloat16_rn(v - __bfloat162float(h));
    }
}

// V transpose+split: g_v [m][1024] -> g_vt{hi,lo} [bh][d][s]
__global__ __launch_bounds__(256)
void vtrans_kernel()
{
    __shared__ float t[64][129];
    const int bh = blockIdx.y, b = bh >> 4, h = bh & 15;
    const int s0 = blockIdx.x * 128;
    const int tid = threadIdx.x;
#pragma unroll
    for (int p = 0; p < 32; p++) {
        const int idx = tid + p * 256;           // 0..8191
        const int d = idx & 63, sl = idx >> 6;   // sl 0..127
        t[d][sl >> 1] = 0.f;                     // (placeholder, overwritten)
        float v = g_v[(size_t)((s0 + sl) * 2 + b) * DMODEL + h * 64 + d];
        if (sl < 64) t[d][sl] = v;               // first half
        else { __syncthreads(); break; }         // unreachable pattern avoided below
    }
    // simpler correct two-pass over 64-wide s chunks:
    for (int half = 0; half < 2; half++) {
        __syncthreads();
#pragma unroll
        for (int p = 0; p < 16; p++) {
            const int idx = tid + p * 256;       // 0..4095
            const int d = idx & 63, sl = idx >> 6;  // sl 0..63
            t[d][sl] = g_v[(size_t)((s0 + half * 64 + sl) * 2 + b) * DMODEL + h * 64 + d];
        }
        __syncthreads();
#pragma unroll
        for (int p = 0; p < 16; p++) {
            const int idx = tid + p * 256;
            const int sl = idx & 63, d = idx >> 6;
            float v = t[d][sl];
            bf16 hi = __float2bfloat16_rn(v);
            bf16 lo = __float2bfloat16_rn(v - __bfloat162float(hi));
            const size_t o = ((size_t)bh * HDIM + d) * S_LEN + s0 + half * 64 + sl;
            g_vthi[o] = hi;
            g_vtlo[o] = lo;
        }
    }
}

// ------------------------------ tcgen05 GEMM -------------------------------
#define GT_M 128
#define GT_N 128
#define GT_K 64
#define NCHUNK (DMODEL / GT_K)
#define TILE_B (GT_M * GT_K * 2)
#define STAGE_B (4 * TILE_B)
#define GEMM_SMEM (2 * STAGE_B + 1024)
#define GT_IDESC ((1u<<4)|(1u<<7)|(1u<<10)|((GT_N/8)<<17)|((GT_M/16)<<24))

#if TC_OK
__device__ __forceinline__ void load_chunk(uint32_t sbase,
    const bf16* __restrict__ Ah, const bf16* __restrict__ Al,
    const bf16* __restrict__ Bh, const bf16* __restrict__ Bl,
    int m0, int n0, int kc, int tid)
{
    const bf16* srcs[4] = { Ah, Al, Bh, Bl };
    const int rb[4] = { m0, m0, n0, n0 };
#pragma unroll
    for (int t = 0; t < 4; t++) {
#pragma unroll
        for (int p = 0; p < 4; p++) {
            const int u = p * 256 + tid;
            const int row = u >> 3, col = u & 7;
            const void* g = srcs[t] + (size_t)(rb[t] + row) * DMODEL + kc * GT_K + col * 8;
            cp16(sbase + t * TILE_B + swz((uint32_t)(u * 16)), g);
        }
    }
}
#endif

// mode 0: fp32 out[m][1024]; mode 1: bf16 hi/lo head layout [bh][s][d]
__device__ __forceinline__ void gemm_core(
    const bf16* __restrict__ Ah, const bf16* __restrict__ Al,
    const bf16* __restrict__ Bh, const bf16* __restrict__ Bl,
    const float* __restrict__ bias, float* __restrict__ outf,
    bf16* __restrict__ outhi, bf16* __restrict__ outlo, int mode,
    char* dyn, uint32_t* s_tmem_p, uint64_t* s_mbar)
{
#if TC_OK
    const int tid = threadIdx.x, wid = tid >> 5, lid = tid & 31;
    const int n0 = blockIdx.x * GT_N, m0 = blockIdx.y * GT_M;

    uint32_t base = smem_u32(dyn);
    base = (base + 1023u) & ~1023u;
    const uint32_t stg0 = base, stg1 = base + STAGE_B;
    const uint32_t mb0 = smem_u32(&s_mbar[0]), mb1 = smem_u32(&s_mbar[1]);

    if (wid == 0) { TCGEN05_ALLOC(smem_u32(s_tmem_p), 128); TCGEN05_RELINQ(); }
    if (tid == 0) { MBARRIER_INIT(mb0, 1); MBARRIER_INIT(mb1, 1); }
    __syncthreads();
    const uint32_t tmem = *s_tmem_p;

    load_chunk(stg0, Ah, Al, Bh, Bl, m0, n0, 0, tid);
    CP_COMMIT();

    uint32_t pc0 = 0, pc1 = 0;
    for (int c = 0; c < NCHUNK; c++) {
        const uint32_t ss = (c & 1) ? stg1 : stg0;
        CP_WAIT0();
        __syncthreads();
        if (wid == 0) {
            const uint64_t dAh = make_desc_sw128(ss);
            const uint64_t dAl = make_desc_sw128(ss + TILE_B);
            const uint64_t dBh = make_desc_sw128(ss + 2 * TILE_B);
            const uint64_t dBl = make_desc_sw128(ss + 3 * TILE_B);
            if (elect_one()) {
                asm volatile("fence.proxy.async.shared::cta;" ::: "memory");
#pragma unroll
                for (int ks = 0; ks < 4; ks++)
                    mma_f16_ss(tmem, dAh + ks * 2, dBh + ks * 2, GT_IDESC,
                               (c == 0 && ks == 0) ? 0u : 1u);
#pragma unroll
                for (int ks = 0; ks < 4; ks++)
                    mma_f16_ss(tmem, dAh + ks * 2, dBl + ks * 2, GT_IDESC, 1u);
#pragma unroll
                for (int ks = 0; ks < 4; ks++)
                    mma_f16_ss(tmem, dAl + ks * 2, dBh + ks * 2, GT_IDESC, 1u);
                TCGEN05_COMMIT((c & 1) ? mb1 : mb0);
            }
        }
        if (c + 1 < NCHUNK) {
            if (c >= 1) {
                if ((c + 1) & 1) { MBAR_WAIT(mb1, pc1); pc1 ^= 1; }
                else             { MBAR_WAIT(mb0, pc0); pc0 ^= 1; }
            }
            load_chunk((c + 1) & 1 ? stg1 : stg0, Ah, Al, Bh, Bl, m0, n0, c + 1, tid);
            CP_COMMIT();
        }
    }
    MBAR_WAIT(mb0, pc0);
    MBAR_WAIT(mb1, pc1);
    TCGEN05_FENCE_AFTER();

    if (wid < 4) {
        const int m = m0 + wid * 32 + lid;
        const int s = m >> 1, b = m & 1;
#pragma unroll
        for (int g = 0; g < 4; g++) {
            uint32_t r[32];
            TCGEN05_LD_X32(r, tmem + g * 32);
            TCGEN05_WAIT_LD();
            const int cb = n0 + g * 32;
            if (mode == 0) {
#pragma unroll
                for (int q = 0; q < 8; q++) {
                    float4 v;
                    v.x = __uint_as_float(r[q * 4 + 0]) + bias[cb + q * 4 + 0];
                    v.y = __uint_as_float(r[q * 4 + 1]) + bias[cb + q * 4 + 1];
                    v.z = __uint_as_float(r[q * 4 + 2]) + bias[cb + q * 4 + 2];
                    v.w = __uint_as_float(r[q * 4 + 3]) + bias[cb + q * 4 + 3];
                    *(float4*)&outf[(size_t)m * DMODEL + cb + q * 4] = v;
                }
            } else {
                const int h = cb >> 6, d0 = cb & 63;
                const size_t ob = ((size_t)(b * NHEADS + h) * S_LEN + s) * HDIM + d0;
#pragma unroll
                for (int q = 0; q < 16; q++) {
                    float v0 = __uint_as_float(r[q * 2 + 0]) + bias[cb + q * 2 + 0];
                    float v1 = __uint_as_float(r[q * 2 + 1]) + bias[cb + q * 2 + 1];
                    __nv_bfloat162 H, L;
                    H.x = __float2bfloat16_rn(v0);
                    H.y = __float2bfloat16_rn(v1);
                    L.x = __float2bfloat16_rn(v0 - __bfloat162float(H.x));
                    L.y = __float2bfloat16_rn(v1 - __bfloat162float(H.y));
                    *(__nv_bfloat162*)&outhi[ob + q * 2] = H;
                    *(__nv_bfloat162*)&outlo[ob + q * 2] = L;
                }
            }
        }
        TCGEN05_FENCE_BEFORE();
    }
    __syncthreads();
    if (wid == 0) TCGEN05_DEALLOC(tmem, 128);
#else
    const int tid = threadIdx.x;
    const int n0 = blockIdx.x * GT_N, m0 = blockIdx.y * GT_M;
    for (int idx = tid; idx < GT_M * GT_N; idx += 256) {
        const int m = m0 + idx / GT_N, n = n0 + idx % GT_N;
        float sacc = bias[n];
        for (int k = 0; k < DMODEL; k++) {
            float a = __bfloat162float(Ah[(size_t)m * DMODEL + k]) +
                      __bfloat162float(Al[(size_t)m * DMODEL + k]);
            float bb = __bfloat162float(Bh[(size_t)n * DMODEL + k]) +
                       __bfloat162float(Bl[(size_t)n * DMODEL + k]);
            sacc = fmaf(a, bb, sacc);
        }
        if (mode == 0) outf[(size_t)m * DMODEL + n] = sacc;
        else {
            const int s = m >> 1, b = m & 1, h = n >> 6, d = n & 63;
            const size_t o = ((size_t)(b * NHEADS + h) * S_LEN + s) * HDIM + d;
            bf16 hv = __float2bfloat16_rn(sacc);
            outhi[o] = hv;
            outlo[o] = __float2bfloat16_rn(sacc - __bfloat162float(hv));
        }
    }
#endif
}

__global__ __launch_bounds__(256, 1)
void qkv_kernel(const float* __restrict__ bq, const float* __restrict__ bk,
                const float* __restrict__ bv)
{
    extern __shared__ char dyn[];
    __shared__ uint32_t s_tmem;
    __shared__ uint64_t s_mbar[2];
    const int z = blockIdx.z;
    const float* bias = (z == 0) ? bq : (z == 1) ? bk : bv;
    if (z == 0)
        gemm_core(g_srchi, g_srclo, g_whi[0], g_wlo[0], bias, nullptr,
                  g_qhi, g_qlo, 1, dyn, &s_tmem, s_mbar);
    else if (z == 1)
        gemm_core(g_srchi, g_srclo, g_whi[1], g_wlo[1], bias, nullptr,
                  g_khi, g_klo, 1, dyn, &s_tmem, s_mbar);
    else
        gemm_core(g_srchi, g_srclo, g_whi[2], g_wlo[2], bias, g_v,
                  nullptr, nullptr, 0, dyn, &s_tmem, s_mbar);
}

__global__ __launch_bounds__(256, 1)
void outproj_kernel(const float* __restrict__ bo, float* __restrict__ out)
{
    extern __shared__ char dyn[];
    __shared__ uint32_t s_tmem;
    __shared__ uint64_t s_mbar[2];
    gemm_core(g_atthi, g_attlo, g_whi[3], g_wlo[3], bo, out,
              nullptr, nullptr, 0, dyn, &s_tmem, s_mbar);
}

// --------------------------- tcgen05 attention -----------------------------
// Per CTA: (b,h), 128-query tile, 16 key-tiles of 128.
// SMEM (dyn, 1024-aligned): QH 16K | QL 16K | K0 hi/lo 32K | K1 32K |
//                           V0 hi/lo 32K | V1 32K | P hi 32K | P lo 32K
#define AQ_H  0
#define AQ_L  16384
#define AK(s) (32768 + (s) * 32768)
#define AV(s) (98304 + (s) * 32768)
#define AP    163840
#define ATTN_DYN (229376 + 1024)
#define IDESC_S  ((1u<<4)|(1u<<7)|(1u<<10)|(16u<<17)|(8u<<24))   // M=128,N=128
#define IDESC_PV ((1u<<4)|(1u<<7)|(1u<<10)|(8u<<17)|(8u<<24))    // M=128,N=64

__global__ __launch_bounds__(256, 1)
void attn_tc_kernel(const float* __restrict__ bias2d)
{
#if TC_OK
    extern __shared__ char dyn[];
    __shared__ uint32_t s_tmem;
    __shared__ uint64_t s_mb[2];
    __shared__ float sm_red[2][128];

    const int tid = threadIdx.x, wid = tid >> 5, lid = tid & 31;
    const int g = wid >> 2;              // warpgroup: key-half 0/1
    const int sp = wid & 3;
    const int row = sp * 32 + lid;       // query row in tile (TMEM lane)
    const int bh = blockIdx.y;
    const int b = bh >> 4, h = bh & 15;
    const int q0 = blockIdx.x * 128;

    uint32_t base = smem_u32(dyn);
    base = (base + 1023u) & ~1023u;
    const uint32_t mbS = smem_u32(&s_mb[0]), mbP = smem_u32(&s_mb[1]);

    if (wid == 0) { TCGEN05_ALLOC(smem_u32(&s_tmem), 256); TCGEN05_RELINQ(); }
    if (tid == 0) { MBARRIER_INIT(mbS, 1); MBARRIER_INIT(mbP, 1); }
    __syncthreads();
    const uint32_t tmem = s_tmem;        // S: cols 0..127, O_tile: 128..191

    const size_t bo_qk = (size_t)bh * S_LEN * HDIM;
    const size_t bo_v  = (size_t)bh * HDIM * S_LEN;

    // ---- prologue: load Q + K/V tile 0 ----
#pragma unroll
    for (int p = 0; p < 4; p++) {
        const int u = p * 256 + tid, r = u >> 3, c = u & 7;
        const size_t go = bo_qk + (size_t)(q0 + r) * HDIM + c * 8;
        cp16(base + AQ_H + swz(u * 16), g_qhi + go);
        cp16(base + AQ_L + swz(u * 16), g_qlo + go);
        const size_t ko = bo_qk + (size_t)r * HDIM + c * 8;
        cp16(base + AK(0) + swz(u * 16), g_khi + ko);
        cp16(base + AK(0) + 16384 + swz(u * 16), g_klo + ko);
    }
#pragma unroll
    for (int p = 0; p < 4; p++) {
        const int u = p * 256 + tid;
        const int c = u >> 9, r = (u >> 3) & 63, sgi = u & 7;
        const size_t vo = bo_v + (size_t)r * S_LEN + c * 64 + sgi * 8;
        const uint32_t doff = c * 8192 + swz((uint32_t)(((u & 511)) * 16));
        cp16(base + AV(0) + doff, g_vthi + vo);
        cp16(base + AV(0) + 16384 + doff, g_vtlo + vo);
    }
    CP_COMMIT(); CP_WAIT0();
    __syncthreads();
    if (wid == 0 && elect_one()) {
        asm volatile("fence.proxy.async.shared::cta;" ::: "memory");
        const uint64_t dQh = make_desc_sw128(base + AQ_H);
        const uint64_t dQl = make_desc_sw128(base + AQ_L);
        const uint64_t dKh = make_desc_sw128(base + AK(0));
        const uint64_t dKl = make_desc_sw128(base + AK(0) + 16384);
#pragma unroll
        for (int ks = 0; ks < 4; ks++) mma_f16_ss(tmem, dQh + ks*2, dKh + ks*2, IDESC_S, ks > 0);
#pragma unroll
        for (int ks = 0; ks < 4; ks++) mma_f16_ss(tmem, dQh + ks*2, dKl + ks*2, IDESC_S, 1);
#pragma unroll
        for (int ks = 0; ks < 4; ks++) mma_f16_ss(tmem, dQl + ks*2, dKh + ks*2, IDESC_S, 1);
        TCGEN05_COMMIT(mbS);
    }

    float m_old = -INFINITY, l = 0.f;
    float O[32];
#pragma unroll
    for (int i = 0; i < 32; i++) O[i] = 0.f;
    uint32_t phS = 0, phP = 0;
    const float* bp = bias2d + (size_t)(q0 + row) * S_LEN + g * 64;

    for (int t = 0; t < 16; t++) {
        const int k0 = t * 128;
        const int stg = t & 1;

        MBAR_WAIT(mbS, phS); phS ^= 1;
        TCGEN05_FENCE_AFTER();
        float sv[64];
        {
            uint32_t r32[32];
            TCGEN05_LD_X32(r32, tmem + g * 64);
            TCGEN05_WAIT_LD();
#pragma unroll
            for (int i = 0; i < 32; i++) sv[i] = __uint_as_float(r32[i]);
            TCGEN05_LD_X32(r32, tmem + g * 64 + 32);
            TCGEN05_WAIT_LD();
#pragma unroll
            for (int i = 0; i < 32; i++) sv[32 + i] = __uint_as_float(r32[i]);
        }
        if (t > 0) { MBAR_WAIT(mbP, phP); phP ^= 1; TCGEN05_FENCE_AFTER(); }

        // prefetch next K/V tile (prev PV done -> stage free)
        if (t < 15) {
            const int nst = (t + 1) & 1, nk0 = k0 + 128;
#pragma unroll
            for (int p = 0; p < 4; p++) {
                const int u = p * 256 + tid, r = u >> 3, c = u & 7;
                const size_t ko = bo_qk + (size_t)(nk0 + r) * HDIM + c * 8;
                cp16(base + AK(nst) + swz(u * 16), g_khi + ko);
                cp16(base + AK(nst) + 16384 + swz(u * 16), g_klo + ko);
            }
#pragma unroll
            for (int p = 0; p < 4; p++) {
                const int u = p * 256 + tid;
                const int c = u >> 9, r = (u >> 3) & 63, sgi = u & 7;
                const size_t vo = bo_v + (size_t)r * S_LEN + nk0 + c * 64 + sgi * 8;
                const uint32_t doff = c * 8192 + swz((uint32_t)((u & 511) * 16));
                cp16(base + AV(nst) + doff, g_vthi + vo);
                cp16(base + AV(nst) + 16384 + doff, g_vtlo + vo);
            }
            CP_COMMIT();
        }

        // logits = s*0.125 + bias; signs; row max
        uint32_t sgA = 0, sgB = 0;
        float rmax = -INFINITY;
#pragma unroll
        for (int j4 = 0; j4 < 16; j4++) {
            float4 bb = *(const float4*)&bp[k0 + j4 * 4];
            float bz[4] = {bb.x, bb.y, bb.z, bb.w};
#pragma unroll
            for (int e = 0; e < 4; e++) {
                const int j = j4 * 4 + e;
                float lg = fmaf(sv[j], 0.125f, bz[e]);
                sv[j] = lg;
                rmax = fmaxf(rmax, lg);
                if (bz[e] < 0.f) { if (j < 32) sgA |= 1u << j; else sgB |= 1u << (j - 32); }
            }
        }
        sm_red[g][row] = rmax;
        __syncthreads();
        const float mn = fmaxf(m_old, fmaxf(rmax, sm_red[1 - g][row]));
        const float alpha = __expf(m_old - mn);
        m_old = mn;
        float lsum = 0.f;
#pragma unroll
        for (int j = 0; j < 64; j++) {
            float e = __expf(sv[j] - mn);
            lsum += e;
            const bool neg = (j < 32) ? ((sgA >> j) & 1u) : ((sgB >> (j - 32)) & 1u);
            sv[j] = neg ? -e : e;
        }
        l = l * alpha + lsum;

        if (t > 0) {
            uint32_t r32[32];
            TCGEN05_LD_X32(r32, tmem + 128 + g * 32);
            TCGEN05_WAIT_LD();
#pragma unroll
            for (int i = 0; i < 32; i++)
                O[i] = (O[i] + __uint_as_float(r32[i])) * alpha;
        }

        // write P (hi/lo) into chunk g
        {
            const uint32_t pbase_h = base + AP + g * 16384;
            const uint32_t pbase_l = base + AP + 32768 + g * 16384;
#pragma unroll
            for (int j = 0; j < 32; j++) {
                float f0 = sv[2 * j], f1 = sv[2 * j + 1];
                __nv_bfloat162 H, L;
                H.x = __float2bfloat16_rn(f0);
                H.y = __float2bfloat16_rn(f1);
                L.x = __float2bfloat16_rn(f0 - __bfloat162float(H.x));
                L.y = __float2bfloat16_rn(f1 - __bfloat162float(H.y));
                const uint32_t off = swz((uint32_t)(row * 128 + j * 4));
                *(uint32_t*)((char*)dyn + (pbase_h + off - smem_u32(dyn))) = *(uint32_t*)&H;
                *(uint32_t*)((char*)dyn + (pbase_l + off - smem_u32(dyn))) = *(uint32_t*)&L;
            }
        }
        CP_WAIT0();
        __syncthreads();

        if (wid == 0 && elect_one()) {
            asm volatile("fence.proxy.async.shared::cta;" ::: "memory");
            // PV(t): O_tile = P * V  (fresh accumulate)
            const uint32_t vst = base + AV(stg);
#pragma unroll
            for (int c = 0; c < 2; c++) {
                const uint64_t dPh = make_desc_sw128(base + AP + c * 16384);
                const uint64_t dPl = make_desc_sw128(base + AP + 32768 + c * 16384);
                const uint64_t dVh = make_desc_sw128(vst + c * 8192);
                const uint64_t dVl = make_desc_sw128(vst + 16384 + c * 8192);
#pragma unroll
                for (int ks = 0; ks < 4; ks++)
                    mma_f16_ss(tmem + 128, dPh + ks*2, dVh + ks*2, IDESC_PV, !(c == 0 && ks == 0));
#pragma unroll
                for (int ks = 0; ks < 4; ks++)
                    mma_f16_ss(tmem + 128, dPh + ks*2, dVl + ks*2, IDESC_PV, 1);
#pragma unroll
                for (int ks = 0; ks < 4; ks++)
                    mma_f16_ss(tmem + 128, dPl + ks*2, dVh + ks*2, IDESC_PV, 1);
            }
            TCGEN05_COMMIT(mbP);
            if (t < 15) {
                const int nst = (t + 1) & 1;
                const uint64_t dQh = make_desc_sw128(base + AQ_H);
                const uint64_t dQl = make_desc_sw128(base + AQ_L);
                const uint64_t dKh = make_desc_sw128(base + AK(nst));
                const uint64_t dKl = make_desc_sw128(base + AK(nst) + 16384);
#pragma unroll
                for (int ks = 0; ks < 4; ks++) mma_f16_ss(tmem, dQh + ks*2, dKh + ks*2, IDESC_S, ks > 0);
#pragma unroll
                for (int ks = 0; ks < 4; ks++) mma_f16_ss(tmem, dQh + ks*2, dKl + ks*2, IDESC_S, 1);
#pragma unroll
                for (int ks = 0; ks < 4; ks++) mma_f16_ss(tmem, dQl + ks*2, dKh + ks*2, IDESC_S, 1);
                TCGEN05_COMMIT(mbS);
            }
        }
    }

    // final: last PV tile + l combine + write
    MBAR_WAIT(mbP, phP);
    TCGEN05_FENCE_AFTER();
    {
        uint32_t r32[32];
        TCGEN05_LD_X32(r32, tmem + 128 + g * 32);
        TCGEN05_WAIT_LD();
#pragma unroll
        for (int i = 0; i < 32; i++) O[i] += __uint_as_float(r32[i]);
    }
    TCGEN05_FENCE_BEFORE();
    __syncthreads();          // sm_red reuse
    sm_red[g][row] = l;
    __syncthreads();
    const float inv = 1.f / (l + sm_red[1 - g][row]);
    const size_t ob = ((size_t)(q0 + row) * 2 + b) * DMODEL + h * 64 + g * 32;
#pragma unroll
    for (int i = 0; i < 16; i++) {
        float v0 = O[2 * i] * inv, v1 = O[2 * i + 1] * inv;
        __nv_bfloat162 H, L;
        H.x = __float2bfloat16_rn(v0);
        H.y = __float2bfloat16_rn(v1);
        L.x = __float2bfloat16_rn(v0 - __bfloat162float(H.x));
        L.y = __float2bfloat16_rn(v1 - __bfloat162float(H.y));
        *(__nv_bfloat162*)&g_atthi[ob + 2 * i] = H;
        *(__nv_bfloat162*)&g_attlo[ob + 2 * i] = L;
    }
    __syncthreads();
    if (wid == 0) TCGEN05_DEALLOC(tmem, 256);
#else
    // naive fallback (generic pass only; never executed on GB300)
    const int tid = threadIdx.x;
    if (tid >= 128) return;
    const int bh = blockIdx.y, b = bh >> 4, h = bh & 15;
    const int q = blockIdx.x * 128 + tid;
    const size_t bo = (size_t)bh * S_LEN * HDIM;
    float m = -INFINITY, l = 0.f, O[64];
    for (int i = 0; i < 64; i++) O[i] = 0.f;
    for (int k = 0; k < S_LEN; k++) {
        float dot = 0.f;
        for (int d = 0; d < 64; d++) {
            float qv = __bfloat162float(g_qhi[bo + (size_t)q * 64 + d]) +
                       __bfloat162float(g_qlo[bo + (size_t)q * 64 + d]);
            float kv = __bfloat162float(g_khi[bo + (size_t)k * 64 + d]) +
                       __bfloat162float(g_klo[bo + (size_t)k * 64 + d]);
            dot = fmaf(qv, kv, dot);
        }
        float bz = bias2d[(size_t)q * S_LEN + k];
        float lg = fmaf(dot, 0.125f, bz);
        float mn = fmaxf(m, lg);
        float al = expf(m - mn);
        float e = expf(lg - mn);
        l = l * al + e;
        float pe = (bz < 0.f) ? -e : e;
        for (int d = 0; d < 64; d++) {
            float vv = g_v[(size_t)(k * 2 + b) * DMODEL + h * 64 + d];
            O[d] = O[d] * al + pe * vv;
        }
        m = mn;
    }
    const size_t ob = ((size_t)q * 2 + b) * DMODEL + h * 64;
    for (int d = 0; d < 64; d++) {
        float v = O[d] / l;
        bf16 hv = __float2bfloat16_rn(v);
        g_atthi[ob + d] = hv;
        g_attlo[ob + d] = __float2bfloat16_rn(v - __bfloat162float(hv));
    }
#endif
}

// ------------------------------ launch -------------------------------------
extern "C" void kernel_launch(void* const* d_in, const int* in_sizes, int n_in,
                              void* d_out, int out_size)
{
    const float* src    = (const float*)d_in[0];
    const float* bias2d = (const float*)d_in[1];
    const float* wq = (const float*)d_in[2];
    const float* bq = (const float*)d_in[3];
    const float* wk = (const float*)d_in[4];
    const float* bk = (const float*)d_in[5];
    const float* wv = (const float*)d_in[6];
    const float* bv = (const float*)d_in[7];
    const float* wo = (const float*)d_in[8];
    const float* bo = (const float*)d_in[9];
    float* out = (float*)d_out;

    cudaFuncSetAttribute(qkv_kernel,
                         cudaFuncAttributeMaxDynamicSharedMemorySize, GEMM_SMEM);
    cudaFuncSetAttribute(outproj_kernel,
                         cudaFuncAttributeMaxDynamicSharedMemorySize, GEMM_SMEM);
    cudaFuncSetAttribute(attn_tc_kernel,
                         cudaFuncAttributeMaxDynamicSharedMemorySize, ATTN_DYN);

    bf16 *srchi, *srclo;
    cudaGetSymbolAddress((void**)&srchi, g_srchi);
    cudaGetSymbolAddress((void**)&srclo, g_srclo);

    split_kernel<<<(M_ROWS * DMODEL / 4) / 256, 256>>>(src, srchi, srclo);
    wprep_kernel<<<dim3(32, 32, 4), dim3(32, 8)>>>(wq, wk, wv, wo);

    dim3 gg(DMODEL / GT_N, M_ROWS / GT_M, 3);
    qkv_kernel<<<gg, 256, GEMM_SMEM>>>(bq, bk, bv);

    vtrans_kernel<<<dim3(S_LEN / 128, NBH), 256>>>();

    attn_tc_kernel<<<dim3(S_LEN / 128, NBH), 256, ATTN_DYN>>>(bias2d);

    dim3 go(DMODEL / GT_N, M_ROWS / GT_M);
    outproj_kernel<<<go, 256, GEMM_SMEM>>>(bo, out);
}

// round 6
// speedup vs baseline: 3.5350x; 1.2046x over previous
#include <cuda_runtime.h>
#include <cuda_bf16.h>
#include <math.h>
#include <stdint.h>
#include <stddef.h>

#define S_LEN  2048
#define BATCH  2
#define DMODEL 1024
#define NHEADS 16
#define HDIM   64
#define M_ROWS 4096
#define NBH    (BATCH * NHEADS)

typedef __nv_bfloat16 bf16;

#if defined(__CUDA_ARCH__) && (defined(__CUDA_ARCH_SPECIFIC__) || \
    defined(__CUDA_ARCH_FEAT_SM103_ALL) || defined(__CUDA_ARCH_FEAT_SM100_ALL))
#define TC_OK 1
#else
#define TC_OK 0
#endif

// ------------------------------ scratch ------------------------------------
__device__ bf16 g_srchi[M_ROWS * DMODEL];
__device__ bf16 g_srclo[M_ROWS * DMODEL];
__device__ bf16 g_whi[4][DMODEL * DMODEL];   // W^T [n][k]
__device__ bf16 g_wlo[4][DMODEL * DMODEL];
__device__ bf16 g_qhi[NBH * S_LEN * HDIM];   // [bh][s][d]
__device__ bf16 g_qlo[NBH * S_LEN * HDIM];
__device__ bf16 g_khi[NBH * S_LEN * HDIM];
__device__ bf16 g_klo[NBH * S_LEN * HDIM];
__device__ float g_v[M_ROWS * DMODEL];       // fp32 [m][c]
__device__ bf16 g_vthi[NBH * HDIM * S_LEN];  // [bh][d][s]
__device__ bf16 g_vtlo[NBH * HDIM * S_LEN];
__device__ bf16 g_atthi[M_ROWS * DMODEL];    // [m][c]
__device__ bf16 g_attlo[M_ROWS * DMODEL];

// ------------------------------ helpers ------------------------------------
__device__ __forceinline__ uint32_t smem_u32(const void* p) {
    uint32_t a;
    asm("{ .reg .u64 t; cvta.to.shared.u64 t, %1; cvt.u32.u64 %0, t; }"
        : "=r"(a) : "l"(p));
    return a;
}
__device__ __forceinline__ void cp16(uint32_t s, const void* g) {
    asm volatile("cp.async.cg.shared.global [%0], [%1], 16;" :: "r"(s), "l"(g));
}
#define CP_COMMIT() asm volatile("cp.async.commit_group;" ::: "memory")
#define CP_WAIT0()  asm volatile("cp.async.wait_group 0;" ::: "memory")
#define CP_WAIT1()  asm volatile("cp.async.wait_group 1;" ::: "memory")
#define MBARRIER_INIT(mb, c) \
    asm volatile("mbarrier.init.shared.b64 [%0], %1;" :: "r"((uint32_t)(mb)), "r"((uint32_t)(c)) : "memory")
#define MBAR_WAIT(mb, par) do {                                                  \
    uint32_t _m = (uint32_t)(mb); uint32_t _p = (uint32_t)(par); uint32_t _d;    \
    asm volatile("{\n\t.reg .pred p;\n\t"                                        \
        "mbarrier.try_wait.parity.acquire.cta.shared::cta.b64 p, [%1], %2;\n\t"  \
        "selp.b32 %0, 1, 0, p;\n\t}" : "=r"(_d) : "r"(_m), "r"(_p) : "memory");  \
    if (!_d) {                                                                   \
        asm volatile("{\n\t.reg .pred P1;\n\tWL_%=:\n\t"                         \
            "mbarrier.try_wait.parity.acquire.cta.shared::cta.b64 P1, [%0], %1, 0x989680;\n\t" \
            "@P1 bra.uni WD_%=;\n\tbra.uni WL_%=;\n\tWD_%=:\n\t}"                \
            :: "r"(_m), "r"(_p) : "memory");                                     \
    } } while (0)
__device__ __forceinline__ uint32_t swz(uint32_t off) {
    return off ^ ((off >> 3) & 0x70);
}

#if TC_OK
__device__ __forceinline__ uint32_t elect_one() {
    uint32_t pred;
    asm volatile("{\n\t.reg .pred p;\n\telect.sync _|p, 0xFFFFFFFF;\n\t"
                 "selp.b32 %0, 1, 0, p;\n\t}" : "=r"(pred));
    return pred;
}
#define TCGEN05_ALLOC(sa, n) \
    asm volatile("tcgen05.alloc.cta_group::1.sync.aligned.shared::cta.b32 [%0], %1;" \
                 :: "r"((uint32_t)(sa)), "r"((uint32_t)(n)) : "memory")
#define TCGEN05_DEALLOC(t, n) \
    asm volatile("tcgen05.dealloc.cta_group::1.sync.aligned.b32 %0, %1;" :: "r"(t), "r"((uint32_t)(n)))
#define TCGEN05_RELINQ() \
    asm volatile("tcgen05.relinquish_alloc_permit.cta_group::1.sync.aligned;")
#define TCGEN05_COMMIT(mb) \
    asm volatile("tcgen05.commit.cta_group::1.mbarrier::arrive::one.shared::cluster.b64 [%0];" \
                 :: "r"((uint32_t)(mb)) : "memory")
#define TCGEN05_FENCE_AFTER()  asm volatile("tcgen05.fence::after_thread_sync;" ::: "memory")
#define TCGEN05_FENCE_BEFORE() asm volatile("tcgen05.fence::before_thread_sync;" ::: "memory")
#define TCGEN05_WAIT_LD()      asm volatile("tcgen05.wait::ld.sync.aligned;" ::: "memory")
#define TCGEN05_LD_X32(r, ta) \
    asm volatile("tcgen05.ld.sync.aligned.32x32b.x32.b32 " \
        "{%0,%1,%2,%3,%4,%5,%6,%7,%8,%9,%10,%11,%12,%13,%14,%15," \
        "%16,%17,%18,%19,%20,%21,%22,%23,%24,%25,%26,%27,%28,%29,%30,%31}, [%32];" \
        : "=r"((r)[0]),"=r"((r)[1]),"=r"((r)[2]),"=r"((r)[3]),"=r"((r)[4]),"=r"((r)[5]),"=r"((r)[6]),"=r"((r)[7]), \
          "=r"((r)[8]),"=r"((r)[9]),"=r"((r)[10]),"=r"((r)[11]),"=r"((r)[12]),"=r"((r)[13]),"=r"((r)[14]),"=r"((r)[15]), \
          "=r"((r)[16]),"=r"((r)[17]),"=r"((r)[18]),"=r"((r)[19]),"=r"((r)[20]),"=r"((r)[21]),"=r"((r)[22]),"=r"((r)[23]), \
          "=r"((r)[24]),"=r"((r)[25]),"=r"((r)[26]),"=r"((r)[27]),"=r"((r)[28]),"=r"((r)[29]),"=r"((r)[30]),"=r"((r)[31]) \
        : "r"(ta))

static __device__ __forceinline__ uint64_t make_desc_sw128(uint32_t base) {
    const uint64_t B = (uint64_t(2) << 61) | (uint64_t(1) << 46)
                     | (uint64_t(64) << 32) | (uint64_t(1) << 16);
    return B | ((uint64_t)(base >> 4) & 0x3FFF);
}
__device__ __forceinline__ void mma_f16_ss(uint32_t d, uint64_t a, uint64_t b,
                                           uint32_t idesc, uint32_t en) {
    asm volatile("{\n\t.reg .pred p;\n\tsetp.ne.u32 p, %5, 0;\n\t"
        "tcgen05.mma.cta_group::1.kind::f16 [%0], %1, %2, %3, {%4,%4,%4,%4}, p;\n\t}"
        :: "r"(d), "l"(a), "l"(b), "r"(idesc), "r"(0u), "r"(en) : "memory");
}
#endif // TC_OK

// ------------------------------ prep kernels -------------------------------
__global__ void split_kernel(const float* __restrict__ in,
                             bf16* __restrict__ hi, bf16* __restrict__ lo)
{
    int i = blockIdx.x * blockDim.x + threadIdx.x;
    float4 x = ((const float4*)in)[i];
    bf16 h0 = __float2bfloat16_rn(x.x), h1 = __float2bfloat16_rn(x.y);
    bf16 h2 = __float2bfloat16_rn(x.z), h3 = __float2bfloat16_rn(x.w);
    __nv_bfloat162 H0; H0.x = h0; H0.y = h1;
    __nv_bfloat162 H1; H1.x = h2; H1.y = h3;
    __nv_bfloat162 L0, L1;
    L0.x = __float2bfloat16_rn(x.x - __bfloat162float(h0));
    L0.y = __float2bfloat16_rn(x.y - __bfloat162float(h1));
    L1.x = __float2bfloat16_rn(x.z - __bfloat162float(h2));
    L1.y = __float2bfloat16_rn(x.w - __bfloat162float(h3));
    ((__nv_bfloat162*)hi)[i * 2] = H0; ((__nv_bfloat162*)hi)[i * 2 + 1] = H1;
    ((__nv_bfloat162*)lo)[i * 2] = L0; ((__nv_bfloat162*)lo)[i * 2 + 1] = L1;
}

__global__ void wprep_kernel(const float* __restrict__ w0, const float* __restrict__ w1,
                             const float* __restrict__ w2, const float* __restrict__ w3)
{
    __shared__ float t[32][33];
    const float* W = (blockIdx.z == 0) ? w0 : (blockIdx.z == 1) ? w1
                   : (blockIdx.z == 2) ? w2 : w3;
    bf16* Whi = g_whi[blockIdx.z];
    bf16* Wlo = g_wlo[blockIdx.z];
    const int n0 = blockIdx.x * 32, k0 = blockIdx.y * 32;
    const int tx = threadIdx.x, ty = threadIdx.y;
#pragma unroll
    for (int i = 0; i < 4; i++)
        t[ty + i * 8][tx] = W[(size_t)(k0 + ty + i * 8) * DMODEL + n0 + tx];
    __syncthreads();
#pragma unroll
    for (int i = 0; i < 4; i++) {
        const int n = n0 + ty + i * 8, k = k0 + tx;
        float v = t[tx][ty + i * 8];
        bf16 h = __float2bfloat16_rn(v);
        Whi[(size_t)n * DMODEL + k] = h;
        Wlo[(size_t)n * DMODEL + k] = __float2bfloat16_rn(v - __bfloat162float(h));
    }
}

// V transpose+split: g_v [m][1024] -> g_vt{hi,lo} [bh][d][s]
__global__ __launch_bounds__(256)
void vtrans_kernel()
{
    __shared__ float t[64][65];
    const int bh = blockIdx.y, b = bh >> 4, h = bh & 15;
    const int s0 = blockIdx.x * 128;
    const int tid = threadIdx.x;
    for (int half = 0; half < 2; half++) {
        __syncthreads();
#pragma unroll
        for (int p = 0; p < 16; p++) {
            const int idx = tid + p * 256;          // 0..4095
            const int d = idx & 63, sl = idx >> 6;  // sl 0..63
            t[d][sl] = g_v[(size_t)((s0 + half * 64 + sl) * 2 + b) * DMODEL + h * 64 + d];
        }
        __syncthreads();
#pragma unroll
        for (int p = 0; p < 16; p++) {
            const int idx = tid + p * 256;
            const int sl = idx & 63, d = idx >> 6;
            float v = t[d][sl];
            bf16 hi = __float2bfloat16_rn(v);
            bf16 lo = __float2bfloat16_rn(v - __bfloat162float(hi));
            const size_t o = ((size_t)bh * HDIM + d) * S_LEN + s0 + half * 64 + sl;
            g_vthi[o] = hi;
            g_vtlo[o] = lo;
        }
    }
}

// ------------------------------ tcgen05 GEMM (3-stage) ---------------------
#define GT_M 128
#define GT_N 128
#define GT_K 64
#define NCHUNK (DMODEL / GT_K)
#define TILE_B (GT_M * GT_K * 2)
#define STAGE_B (4 * TILE_B)              // 64 KB
#define GEMM_SMEM (3 * STAGE_B + 1024)
#define GT_IDESC ((1u<<4)|(1u<<7)|(1u<<10)|((GT_N/8)<<17)|((GT_M/16)<<24))

#if TC_OK
__device__ __forceinline__ void load_chunk(uint32_t sbase,
    const bf16* __restrict__ Ah, const bf16* __restrict__ Al,
    const bf16* __restrict__ Bh, const bf16* __restrict__ Bl,
    int m0, int n0, int kc, int tid)
{
    const bf16* srcs[4] = { Ah, Al, Bh, Bl };
    const int rb[4] = { m0, m0, n0, n0 };
#pragma unroll
    for (int t = 0; t < 4; t++) {
#pragma unroll
        for (int p = 0; p < 4; p++) {
            const int u = p * 256 + tid;
            const int row = u >> 3, col = u & 7;
            const void* g = srcs[t] + (size_t)(rb[t] + row) * DMODEL + kc * GT_K + col * 8;
            cp16(sbase + t * TILE_B + swz((uint32_t)(u * 16)), g);
        }
    }
}
#endif

// mode 0: fp32 out[m][1024]; mode 1: bf16 hi/lo head layout [bh][s][d]
__device__ __forceinline__ void gemm_core(
    const bf16* __restrict__ Ah, const bf16* __restrict__ Al,
    const bf16* __restrict__ Bh, const bf16* __restrict__ Bl,
    const float* __restrict__ bias, float* __restrict__ outf,
    bf16* __restrict__ outhi, bf16* __restrict__ outlo, int mode,
    char* dyn, uint32_t* s_tmem_p, uint64_t* s_mbar)
{
#if TC_OK
    const int tid = threadIdx.x, wid = tid >> 5, lid = tid & 31;
    const int n0 = blockIdx.x * GT_N, m0 = blockIdx.y * GT_M;

    uint32_t base = smem_u32(dyn);
    base = (base + 1023u) & ~1023u;
    const uint32_t mb[3] = { smem_u32(&s_mbar[0]), smem_u32(&s_mbar[1]),
                             smem_u32(&s_mbar[2]) };

    if (wid == 0) { TCGEN05_ALLOC(smem_u32(s_tmem_p), 128); TCGEN05_RELINQ(); }
    if (tid == 0) { MBARRIER_INIT(mb[0], 1); MBARRIER_INIT(mb[1], 1); MBARRIER_INIT(mb[2], 1); }
    __syncthreads();
    const uint32_t tmem = *s_tmem_p;

    load_chunk(base, Ah, Al, Bh, Bl, m0, n0, 0, tid); CP_COMMIT();
    load_chunk(base + STAGE_B, Ah, Al, Bh, Bl, m0, n0, 1, tid); CP_COMMIT();

    for (int c = 0; c < NCHUNK; c++) {
        const uint32_t ss = base + (uint32_t)(c % 3) * STAGE_B;
        CP_WAIT1();                 // chunk c loaded (c+1 may be outstanding)
        __syncthreads();
        if (wid == 0) {
            const uint64_t dAh = make_desc_sw128(ss);
            const uint64_t dAl = make_desc_sw128(ss + TILE_B);
            const uint64_t dBh = make_desc_sw128(ss + 2 * TILE_B);
            const uint64_t dBl = make_desc_sw128(ss + 3 * TILE_B);
            if (elect_one()) {
                asm volatile("fence.proxy.async.shared::cta;" ::: "memory");
#pragma unroll
                for (int ks = 0; ks < 4; ks++)
                    mma_f16_ss(tmem, dAh + ks * 2, dBh + ks * 2, GT_IDESC,
                               (c == 0 && ks == 0) ? 0u : 1u);
#pragma unroll
                for (int ks = 0; ks < 4; ks++)
                    mma_f16_ss(tmem, dAh + ks * 2, dBl + ks * 2, GT_IDESC, 1u);
#pragma unroll
                for (int ks = 0; ks < 4; ks++)
                    mma_f16_ss(tmem, dAl + ks * 2, dBh + ks * 2, GT_IDESC, 1u);
                TCGEN05_COMMIT(mb[c % 3]);
            }
        }
        if (c + 2 < NCHUNK) {
            if (c >= 1)
                MBAR_WAIT(mb[(c - 1) % 3], ((c - 1) / 3) & 1);   // stage (c+2)%3 free
            load_chunk(base + (uint32_t)((c + 2) % 3) * STAGE_B,
                       Ah, Al, Bh, Bl, m0, n0, c + 2, tid);
        }
        CP_COMMIT();   // always commit (possibly empty group)
    }
    MBAR_WAIT(mb[13 % 3], (13 / 3) & 1);
    MBAR_WAIT(mb[14 % 3], (14 / 3) & 1);
    MBAR_WAIT(mb[15 % 3], (15 / 3) & 1);
    TCGEN05_FENCE_AFTER();

    if (wid < 4) {
        const int m = m0 + wid * 32 + lid;
        const int s = m >> 1, b = m & 1;
#pragma unroll
        for (int g = 0; g < 4; g++) {
            uint32_t r[32];
            TCGEN05_LD_X32(r, tmem + g * 32);
            TCGEN05_WAIT_LD();
            const int cb = n0 + g * 32;
            if (mode == 0) {
#pragma unroll
                for (int q = 0; q < 8; q++) {
                    float4 v;
                    v.x = __uint_as_float(r[q * 4 + 0]) + bias[cb + q * 4 + 0];
                    v.y = __uint_as_float(r[q * 4 + 1]) + bias[cb + q * 4 + 1];
                    v.z = __uint_as_float(r[q * 4 + 2]) + bias[cb + q * 4 + 2];
                    v.w = __uint_as_float(r[q * 4 + 3]) + bias[cb + q * 4 + 3];
                    *(float4*)&outf[(size_t)m * DMODEL + cb + q * 4] = v;
                }
            } else {
                const int h = cb >> 6, d0 = cb & 63;
                const size_t ob = ((size_t)(b * NHEADS + h) * S_LEN + s) * HDIM + d0;
#pragma unroll
                for (int q = 0; q < 16; q++) {
                    float v0 = __uint_as_float(r[q * 2 + 0]) + bias[cb + q * 2 + 0];
                    float v1 = __uint_as_float(r[q * 2 + 1]) + bias[cb + q * 2 + 1];
                    __nv_bfloat162 H, L;
                    H.x = __float2bfloat16_rn(v0);
                    H.y = __float2bfloat16_rn(v1);
                    L.x = __float2bfloat16_rn(v0 - __bfloat162float(H.x));
                    L.y = __float2bfloat16_rn(v1 - __bfloat162float(H.y));
                    *(__nv_bfloat162*)&outhi[ob + q * 2] = H;
                    *(__nv_bfloat162*)&outlo[ob + q * 2] = L;
                }
            }
        }
        TCGEN05_FENCE_BEFORE();
    }
    __syncthreads();
    if (wid == 0) TCGEN05_DEALLOC(tmem, 128);
#else
    const int tid = threadIdx.x;
    const int n0 = blockIdx.x * GT_N, m0 = blockIdx.y * GT_M;
    for (int idx = tid; idx < GT_M * GT_N; idx += 256) {
        const int m = m0 + idx / GT_N, n = n0 + idx % GT_N;
        float sacc = bias[n];
        for (int k = 0; k < DMODEL; k++) {
            float a = __bfloat162float(Ah[(size_t)m * DMODEL + k]) +
                      __bfloat162float(Al[(size_t)m * DMODEL + k]);
            float bb = __bfloat162float(Bh[(size_t)n * DMODEL + k]) +
                       __bfloat162float(Bl[(size_t)n * DMODEL + k]);
            sacc = fmaf(a, bb, sacc);
        }
        if (mode == 0) outf[(size_t)m * DMODEL + n] = sacc;
        else {
            const int s = m >> 1, b = m & 1, h = n >> 6, d = n & 63;
            const size_t o = ((size_t)(b * NHEADS + h) * S_LEN + s) * HDIM + d;
            bf16 hv = __float2bfloat16_rn(sacc);
            outhi[o] = hv;
            outlo[o] = __float2bfloat16_rn(sacc - __bfloat162float(hv));
        }
    }
#endif
}

__global__ __launch_bounds__(256, 1)
void qkv_kernel(const float* __restrict__ bq, const float* __restrict__ bk,
                const float* __restrict__ bv)
{
    extern __shared__ char dyn[];
    __shared__ uint32_t s_tmem;
    __shared__ uint64_t s_mbar[3];
    const int z = blockIdx.z;
    if (z == 0)
        gemm_core(g_srchi, g_srclo, g_whi[0], g_wlo[0], bq, nullptr,
                  g_qhi, g_qlo, 1, dyn, &s_tmem, s_mbar);
    else if (z == 1)
        gemm_core(g_srchi, g_srclo, g_whi[1], g_wlo[1], bk, nullptr,
                  g_khi, g_klo, 1, dyn, &s_tmem, s_mbar);
    else
        gemm_core(g_srchi, g_srclo, g_whi[2], g_wlo[2], bv, g_v,
                  nullptr, nullptr, 0, dyn, &s_tmem, s_mbar);
}

__global__ __launch_bounds__(256, 1)
void outproj_kernel(const float* __restrict__ bo, float* __restrict__ out)
{
    extern __shared__ char dyn[];
    __shared__ uint32_t s_tmem;
    __shared__ uint64_t s_mbar[3];
    gemm_core(g_atthi, g_attlo, g_whi[3], g_wlo[3], bo, out,
              nullptr, nullptr, 0, dyn, &s_tmem, s_mbar);
}

// --------------------------- tcgen05 attention -----------------------------
// TMEM: S0 @cols 0-127, S1 @128-255 (double-buffered), O @256-319.
#define AQ_H  0
#define AQ_L  16384
#define AK(s) (32768 + (s) * 32768)
#define AV(s) (98304 + (s) * 32768)
#define AP    163840
#define ATTN_DYN (229376 + 1024)
#define IDESC_S  ((1u<<4)|(1u<<7)|(1u<<10)|(16u<<17)|(8u<<24))   // M=128,N=128
#define IDESC_PV ((1u<<4)|(1u<<7)|(1u<<10)|(8u<<17)|(8u<<24))    // M=128,N=64

__global__ __launch_bounds__(256, 1)
void attn_tc_kernel(const float* __restrict__ bias2d)
{
#if TC_OK
    extern __shared__ char dyn[];
    __shared__ uint32_t s_tmem;
    __shared__ uint64_t s_mb[2];
    __shared__ float sm_red[2][128];

    const int tid = threadIdx.x, wid = tid >> 5, lid = tid & 31;
    const int g = wid >> 2;              // warpgroup: key-half 0/1
    const int sp = wid & 3;
    const int row = sp * 32 + lid;       // query row in tile (TMEM lane)
    const int bh = blockIdx.y;
    const int b = bh >> 4, h = bh & 15;
    const int q0 = blockIdx.x * 128;

    uint32_t base = smem_u32(dyn);
    base = (base + 1023u) & ~1023u;
    char* smp = dyn + (ptrdiff_t)(base - smem_u32(dyn));
    const uint32_t mbS = smem_u32(&s_mb[0]), mbP = smem_u32(&s_mb[1]);

    if (wid == 0) { TCGEN05_ALLOC(smem_u32(&s_tmem), 512); TCGEN05_RELINQ(); }
    if (tid == 0) { MBARRIER_INIT(mbS, 1); MBARRIER_INIT(mbP, 1); }
    __syncthreads();
    const uint32_t tmem = s_tmem;

    const size_t bo_qk = (size_t)bh * S_LEN * HDIM;
    const size_t bo_v  = (size_t)bh * HDIM * S_LEN;

    // ---- prologue: load Q + K/V tile 0, issue S(0) ----
#pragma unroll
    for (int p = 0; p < 4; p++) {
        const int u = p * 256 + tid, r = u >> 3, c = u & 7;
        const size_t go = bo_qk + (size_t)(q0 + r) * HDIM + c * 8;
        cp16(base + AQ_H + swz(u * 16), g_qhi + go);
        cp16(base + AQ_L + swz(u * 16), g_qlo + go);
        const size_t ko = bo_qk + (size_t)r * HDIM + c * 8;
        cp16(base + AK(0) + swz(u * 16), g_khi + ko);
        cp16(base + AK(0) + 16384 + swz(u * 16), g_klo + ko);
    }
#pragma unroll
    for (int p = 0; p < 4; p++) {
        const int u = p * 256 + tid;
        const int c = u >> 9, r = (u >> 3) & 63, sgi = u & 7;
        const size_t vo = bo_v + (size_t)r * S_LEN + c * 64 + sgi * 8;
        const uint32_t doff = c * 8192 + swz((uint32_t)((u & 511) * 16));
        cp16(base + AV(0) + doff, g_vthi + vo);
        cp16(base + AV(0) + 16384 + doff, g_vtlo + vo);
    }
    CP_COMMIT(); CP_WAIT0();
    __syncthreads();
    if (wid == 0 && elect_one()) {
        asm volatile("fence.proxy.async.shared::cta;" ::: "memory");
        const uint64_t dQh = make_desc_sw128(base + AQ_H);
        const uint64_t dQl = make_desc_sw128(base + AQ_L);
        const uint64_t dKh = make_desc_sw128(base + AK(0));
        const uint64_t dKl = make_desc_sw128(base + AK(0) + 16384);
#pragma unroll
        for (int ks = 0; ks < 4; ks++) mma_f16_ss(tmem, dQh + ks*2, dKh + ks*2, IDESC_S, ks > 0);
#pragma unroll
        for (int ks = 0; ks < 4; ks++) mma_f16_ss(tmem, dQh + ks*2, dKl + ks*2, IDESC_S, 1);
#pragma unroll
        for (int ks = 0; ks < 4; ks++) mma_f16_ss(tmem, dQl + ks*2, dKh + ks*2, IDESC_S, 1);
        TCGEN05_COMMIT(mbS);
    }

    float m_old = -INFINITY, l = 0.f;
    float O[32];
#pragma unroll
    for (int i = 0; i < 32; i++) O[i] = 0.f;
    uint32_t phS = 0, phP = 0;
    const float* bp = bias2d + (size_t)(q0 + row) * S_LEN + g * 64;

    for (int t = 0; t < 16; t++) {
        const int k0 = t * 128;
        const int stg = t & 1;

        // --- S(t) ready ---
        MBAR_WAIT(mbS, phS); phS ^= 1;
        TCGEN05_FENCE_AFTER();
        float sv[64];
        {
            uint32_t r32[32];
            TCGEN05_LD_X32(r32, tmem + stg * 128 + g * 64);
            TCGEN05_WAIT_LD();
#pragma unroll
            for (int i = 0; i < 32; i++) sv[i] = __uint_as_float(r32[i]);
            TCGEN05_LD_X32(r32, tmem + stg * 128 + g * 64 + 32);
            TCGEN05_WAIT_LD();
#pragma unroll
            for (int i = 0; i < 32; i++) sv[32 + i] = __uint_as_float(r32[i]);
            TCGEN05_FENCE_BEFORE();
        }

        // --- logits + row max ---
        uint32_t sgA = 0, sgB = 0;
        float rmax = -INFINITY;
#pragma unroll
        for (int j4 = 0; j4 < 16; j4++) {
            float4 bb = *(const float4*)&bp[k0 + j4 * 4];
            float bz[4] = {bb.x, bb.y, bb.z, bb.w};
#pragma unroll
            for (int e = 0; e < 4; e++) {
                const int j = j4 * 4 + e;
                float lg = fmaf(sv[j], 0.125f, bz[e]);
                sv[j] = lg;
                rmax = fmaxf(rmax, lg);
                if (bz[e] < 0.f) { if (j < 32) sgA |= 1u << j; else sgB |= 1u << (j - 32); }
            }
        }
        sm_red[g][row] = rmax;

        // --- PV(t-1) done -> KV stage (t+1)&1 free; prefetch KV(t+1) ---
        if (t > 0) { MBAR_WAIT(mbP, phP); phP ^= 1; TCGEN05_FENCE_AFTER(); }
        if (t < 15) {
            const int nst = (t + 1) & 1, nk0 = k0 + 128;
#pragma unroll
            for (int p = 0; p < 4; p++) {
                const int u = p * 256 + tid, r = u >> 3, c = u & 7;
                const size_t ko = bo_qk + (size_t)(nk0 + r) * HDIM + c * 8;
                cp16(base + AK(nst) + swz(u * 16), g_khi + ko);
                cp16(base + AK(nst) + 16384 + swz(u * 16), g_klo + ko);
            }
#pragma unroll
            for (int p = 0; p < 4; p++) {
                const int u = p * 256 + tid;
                const int c = u >> 9, r = (u >> 3) & 63, sgi = u & 7;
                const size_t vo = bo_v + (size_t)r * S_LEN + nk0 + c * 64 + sgi * 8;
                const uint32_t doff = c * 8192 + swz((uint32_t)((u & 511) * 16));
                cp16(base + AV(nst) + doff, g_vthi + vo);
                cp16(base + AV(nst) + 16384 + doff, g_vtlo + vo);
            }
            CP_COMMIT();
        }

        // --- O partial from PV(t-1) ---
        float tg[32];
        if (t > 0) {
            uint32_t r32[32];
            TCGEN05_LD_X32(r32, tmem + 256 + g * 32);
            TCGEN05_WAIT_LD();
#pragma unroll
            for (int i = 0; i < 32; i++) tg[i] = __uint_as_float(r32[i]);
            TCGEN05_FENCE_BEFORE();
        }
        __syncthreads();   // sm_red visible

        const float mn = fmaxf(m_old, fmaxf(rmax, sm_red[1 - g][row]));
        const float alpha = __expf(m_old - mn);
        m_old = mn;
        float lsum = 0.f;
#pragma unroll
        for (int j = 0; j < 64; j++) {
            float e = __expf(sv[j] - mn);
            lsum += e;
            const bool neg = (j < 32) ? ((sgA >> j) & 1u) : ((sgB >> (j - 32)) & 1u);
            sv[j] = neg ? -e : e;
        }
        l = l * alpha + lsum;
        if (t > 0) {
#pragma unroll
            for (int i = 0; i < 32; i++) O[i] = (O[i] + tg[i]) * alpha;
        }

        // --- early S(t+1) issue (K(t+1) now in smem; S buffer ^1 free) ---
        if (t < 15) {
            CP_WAIT0();
            __syncthreads();
            if (wid == 0 && elect_one()) {
                asm volatile("fence.proxy.async.shared::cta;" ::: "memory");
                TCGEN05_FENCE_AFTER();
                const int nst = (t + 1) & 1;
                const uint64_t dQh = make_desc_sw128(base + AQ_H);
                const uint64_t dQl = make_desc_sw128(base + AQ_L);
                const uint64_t dKh = make_desc_sw128(base + AK(nst));
                const uint64_t dKl = make_desc_sw128(base + AK(nst) + 16384);
                const uint32_t sd = tmem + nst * 128;
#pragma unroll
                for (int ks = 0; ks < 4; ks++) mma_f16_ss(sd, dQh + ks*2, dKh + ks*2, IDESC_S, ks > 0);
#pragma unroll
                for (int ks = 0; ks < 4; ks++) mma_f16_ss(sd, dQh + ks*2, dKl + ks*2, IDESC_S, 1);
#pragma unroll
                for (int ks = 0; ks < 4; ks++) mma_f16_ss(sd, dQl + ks*2, dKh + ks*2, IDESC_S, 1);
                TCGEN05_COMMIT(mbS);
            }
        }

        // --- write P (hi/lo, STS.128) ---
        {
            const int pco = AP + g * 16384;
#pragma unroll
            for (int jg = 0; jg < 8; jg++) {
                uint32_t H[4], L[4];
#pragma unroll
                for (int e = 0; e < 4; e++) {
                    float f0 = sv[jg * 8 + e * 2], f1 = sv[jg * 8 + e * 2 + 1];
                    __nv_bfloat162 hh, ll;
                    hh.x = __float2bfloat16_rn(f0);
                    hh.y = __float2bfloat16_rn(f1);
                    ll.x = __float2bfloat16_rn(f0 - __bfloat162float(hh.x));
                    ll.y = __float2bfloat16_rn(f1 - __bfloat162float(hh.y));
                    H[e] = *(uint32_t*)&hh;
                    L[e] = *(uint32_t*)&ll;
                }
                const uint32_t off = swz((uint32_t)(row * 128 + jg * 16));
                *(uint4*)(smp + pco + off) = make_uint4(H[0], H[1], H[2], H[3]);
                *(uint4*)(smp + pco + 32768 + off) = make_uint4(L[0], L[1], L[2], L[3]);
            }
        }
        __syncthreads();

        // --- PV(t): overwrite O accumulator ---
        if (wid == 0 && elect_one()) {
            asm volatile("fence.proxy.async.shared::cta;" ::: "memory");
            TCGEN05_FENCE_AFTER();
            const uint32_t vst = base + AV(stg);
#pragma unroll
            for (int c = 0; c < 2; c++) {
                const uint64_t dPh = make_desc_sw128(base + AP + c * 16384);
                const uint64_t dPl = make_desc_sw128(base + AP + 32768 + c * 16384);
                const uint64_t dVh = make_desc_sw128(vst + c * 8192);
                const uint64_t dVl = make_desc_sw128(vst + 16384 + c * 8192);
#pragma unroll
                for (int ks = 0; ks < 4; ks++)
                    mma_f16_ss(tmem + 256, dPh + ks*2, dVh + ks*2, IDESC_PV, !(c == 0 && ks == 0));
#pragma unroll
                for (int ks = 0; ks < 4; ks++)
                    mma_f16_ss(tmem + 256, dPh + ks*2, dVl + ks*2, IDESC_PV, 1);
#pragma unroll
                for (int ks = 0; ks < 4; ks++)
                    mma_f16_ss(tmem + 256, dPl + ks*2, dVh + ks*2, IDESC_PV, 1);
            }
            TCGEN05_COMMIT(mbP);
        }
    }

    // --- final: last PV tile + l combine + write ---
    MBAR_WAIT(mbP, phP);
    TCGEN05_FENCE_AFTER();
    {
        uint32_t r32[32];
        TCGEN05_LD_X32(r32, tmem + 256 + g * 32);
        TCGEN05_WAIT_LD();
#pragma unroll
        for (int i = 0; i < 32; i++) O[i] += __uint_as_float(r32[i]);
    }
    TCGEN05_FENCE_BEFORE();
    __syncthreads();
    sm_red[g][row] = l;
    __syncthreads();
    const float inv = 1.f / (l + sm_red[1 - g][row]);
    const size_t ob = ((size_t)(q0 + row) * 2 + b) * DMODEL + h * 64 + g * 32;
#pragma unroll
    for (int i = 0; i < 16; i++) {
        float v0 = O[2 * i] * inv, v1 = O[2 * i + 1] * inv;
        __nv_bfloat162 H, L;
        H.x = __float2bfloat16_rn(v0);
        H.y = __float2bfloat16_rn(v1);
        L.x = __float2bfloat16_rn(v0 - __bfloat162float(H.x));
        L.y = __float2bfloat16_rn(v1 - __bfloat162float(H.y));
        *(__nv_bfloat162*)&g_atthi[ob + 2 * i] = H;
        *(__nv_bfloat162*)&g_attlo[ob + 2 * i] = L;
    }
    __syncthreads();
    if (wid == 0) TCGEN05_DEALLOC(tmem, 512);
#else
    // naive fallback (generic pass only; never executed on GB300)
    const int tid = threadIdx.x;
    if (tid >= 128) return;
    const int bh = blockIdx.y, b = bh >> 4, h = bh & 15;
    const int q = blockIdx.x * 128 + tid;
    const size_t bo = (size_t)bh * S_LEN * HDIM;
    float m = -INFINITY, l = 0.f, O[64];
    for (int i = 0; i < 64; i++) O[i] = 0.f;
    for (int k = 0; k < S_LEN; k++) {
        float dot = 0.f;
        for (int d = 0; d < 64; d++) {
            float qv = __bfloat162float(g_qhi[bo + (size_t)q * 64 + d]) +
                       __bfloat162float(g_qlo[bo + (size_t)q * 64 + d]);
            float kv = __bfloat162float(g_khi[bo + (size_t)k * 64 + d]) +
                       __bfloat162float(g_klo[bo + (size_t)k * 64 + d]);
            dot = fmaf(qv, kv, dot);
        }
        float bz = bias2d[(size_t)q * S_LEN + k];
        float lg = fmaf(dot, 0.125f, bz);
        float mn = fmaxf(m, lg);
        float al = expf(m - mn);
        float e = expf(lg - mn);
        l = l * al + e;
        float pe = (bz < 0.f) ? -e : e;
        for (int d = 0; d < 64; d++) {
            float vv = g_v[(size_t)(k * 2 + b) * DMODEL + h * 64 + d];
            O[d] = O[d] * al + pe * vv;
        }
        m = mn;
    }
    const size_t ob = ((size_t)q * 2 + b) * DMODEL + h * 64;
    for (int d = 0; d < 64; d++) {
        float v = O[d] / l;
        bf16 hv = __float2bfloat16_rn(v);
        g_atthi[ob + d] = hv;
        g_attlo[ob + d] = __float2bfloat16_rn(v - __bfloat162float(hv));
    }
#endif
}

// ------------------------------ launch -------------------------------------
extern "C" void kernel_launch(void* const* d_in, const int* in_sizes, int n_in,
                              void* d_out, int out_size)
{
    const float* src    = (const float*)d_in[0];
    const float* bias2d = (const float*)d_in[1];
    const float* wq = (const float*)d_in[2];
    const float* bq = (const float*)d_in[3];
    const float* wk = (const float*)d_in[4];
    const float* bk = (const float*)d_in[5];
    const float* wv = (const float*)d_in[6];
    const float* bv = (const float*)d_in[7];
    const float* wo = (const float*)d_in[8];
    const float* bo = (const float*)d_in[9];
    float* out = (float*)d_out;

    cudaFuncSetAttribute(qkv_kernel,
                         cudaFuncAttributeMaxDynamicSharedMemorySize, GEMM_SMEM);
    cudaFuncSetAttribute(outproj_kernel,
                         cudaFuncAttributeMaxDynamicSharedMemorySize, GEMM_SMEM);
    cudaFuncSetAttribute(attn_tc_kernel,
                         cudaFuncAttributeMaxDynamicSharedMemorySize, ATTN_DYN);

    bf16 *srchi, *srclo;
    cudaGetSymbolAddress((void**)&srchi, g_srchi);
    cudaGetSymbolAddress((void**)&srclo, g_srclo);

    split_kernel<<<(M_ROWS * DMODEL / 4) / 256, 256>>>(src, srchi, srclo);
    wprep_kernel<<<dim3(32, 32, 4), dim3(32, 8)>>>(wq, wk, wv, wo);

    dim3 gg(DMODEL / GT_N, M_ROWS / GT_M, 3);
    qkv_kernel<<<gg, 256, GEMM_SMEM>>>(bq, bk, bv);

    vtrans_kernel<<<dim3(S_LEN / 128, NBH), 256>>>();

    attn_tc_kernel<<<dim3(S_LEN / 128, NBH), 256, ATTN_DYN>>>(bias2d);

    dim3 go(DMODEL / GT_N, M_ROWS / GT_M);
    outproj_kernel<<<go, 256, GEMM_SMEM>>>(bo, out);
}